// round 1
// baseline (speedup 1.0000x reference)
#include <cuda_runtime.h>
#include <math.h>

#define L 256
#define C 1024
#define NEC 2000
#define NPAIR 65536

// Scratch (allocation-guard-safe: __device__ globals, no cudaMalloc anywhere)
__device__ float g_mask[L];
__device__ float g_z[C * L];                 // z[c][l], masked, transposed
__device__ float g_tmp[C];                   // lin1 output
__device__ float g_h[(size_t)C * NPAIR];     // h[o][i][j]  (268 MB)
__device__ float g_part[16 * NPAIR];         // conv2 channel-group partials

// ---------------- prep: mask + masked transpose ----------------
__global__ void k_mask(const int* __restrict__ am) {
    __shared__ int red[256];
    int l = threadIdx.x;
    int v = am[l];
    red[l] = v;
    __syncthreads();
    for (int off = 128; off; off >>= 1) {
        if (l < off) red[l] += red[l + off];
        __syncthreads();
    }
    int s = red[0];                 // sum of mask; position s gets zeroed (SEP)
    float m = (float)v;
    if (l == 0 || l == s) m = 0.f;  // CLS + SEP masked out
    g_mask[l] = m;
}

__global__ void k_z(const float* __restrict__ attn) {
    int l = blockIdx.x;
    float m = g_mask[l];
    for (int c = threadIdx.x; c < C; c += blockDim.x)
        g_z[c * L + l] = attn[l * C + c] * m;
}

// ---------------- logits head (two GEMVs, warp-per-output) ----------------
__global__ void k_lin1(const float* __restrict__ pooled, const float* __restrict__ w,
                       const float* __restrict__ b) {
    int gw = (blockIdx.x * blockDim.x + threadIdx.x) >> 5;
    int lane = threadIdx.x & 31;
    if (gw >= C) return;
    const float* row = w + (size_t)gw * C;
    float s = 0.f;
    for (int c2 = lane; c2 < C; c2 += 32) s += row[c2] * pooled[c2];
#pragma unroll
    for (int off = 16; off; off >>= 1) s += __shfl_xor_sync(0xffffffffu, s, off);
    if (lane == 0) g_tmp[gw] = s + b[gw];
}

__global__ void k_cls(const float* __restrict__ w, const float* __restrict__ b,
                      float* __restrict__ out) {
    int gw = (blockIdx.x * blockDim.x + threadIdx.x) >> 5;
    int lane = threadIdx.x & 31;
    if (gw >= NEC) return;
    const float* row = w + (size_t)gw * C;
    float s = 0.f;
    for (int c2 = lane; c2 < C; c2 += 32) s += row[c2] * g_tmp[c2];
#pragma unroll
    for (int off = 16; off; off >>= 1) s += __shfl_xor_sync(0xffffffffu, s, off);
    if (lane == 0) out[gw] = s + b[gw];
}

// ---------------- main: h = relu(W1 @ |zi-zj| + W2 @ (zi*zj) + b) ----------------
// Block: 128 o x (8 i x 8 j) pairs. Only upper-triangular (jb >= ib) pair blocks.
// Thread: 8 o x 4 pairs. K-loop over 1024 channels in chunks of 8, reg-prefetched.
__global__ __launch_bounds__(256) void k_h(const float* __restrict__ W,
                                           const float* __restrict__ b1) {
    int ib = blockIdx.y, jb = blockIdx.z;
    if (jb < ib) return;               // symmetry: compute upper triangle only
    int o0 = blockIdx.x * 128;
    int i0 = ib * 8, j0 = jb * 8;

    __shared__ __align__(16) float sW1[8][132];  // [c][o], pad 4 -> conflict-free stores
    __shared__ __align__(16) float sW2[8][132];
    __shared__ __align__(16) float sZi[8][8];
    __shared__ __align__(16) float sZj[8][8];

    int tid = threadIdx.x;
    int tx = tid & 15, ty = tid >> 4;
    int om = ty * 8;
    int il = tx >> 1;
    int jl0 = (tx & 1) * 4;

    // W load pointers: t -> (o = t>>3, c = t&7); W2 lives at column offset +1024
    const float* wp[4];
#pragma unroll
    for (int r = 0; r < 4; r++) {
        int t = tid + r * 256;
        wp[r] = W + (size_t)(o0 + (t >> 3)) * 2048 + (t & 7);
    }
    const float* zp = g_z;  // valid base; only tid<128 uses real offsets
    if (tid < 64)       zp = g_z + (tid >> 3) * L + i0 + (tid & 7);
    else if (tid < 128) zp = g_z + ((tid - 64) >> 3) * L + j0 + (tid & 7);

    float acc[8][4];
#pragma unroll
    for (int a = 0; a < 8; a++)
#pragma unroll
        for (int t = 0; t < 4; t++) acc[a][t] = 0.f;

    // preload chunk 0
    float pw1[4], pw2[4], pz = 0.f;
#pragma unroll
    for (int r = 0; r < 4; r++) { pw1[r] = wp[r][0]; pw2[r] = wp[r][1024]; }
    if (tid < 128) pz = zp[0];
#pragma unroll
    for (int r = 0; r < 4; r++) {
        int t = tid + r * 256;
        sW1[t & 7][t >> 3] = pw1[r];
        sW2[t & 7][t >> 3] = pw2[r];
    }
    if (tid < 64)       sZi[tid >> 3][tid & 7] = pz;
    else if (tid < 128) sZj[(tid - 64) >> 3][tid & 7] = pz;
    __syncthreads();

    for (int kk = 0; kk < 128; kk++) {           // 128 chunks x 8 channels = 1024
        int c0 = (kk + 1) * 8;
        float nw1[4], nw2[4], nz = 0.f;
        if (kk < 127) {
#pragma unroll
            for (int r = 0; r < 4; r++) { nw1[r] = wp[r][c0]; nw2[r] = wp[r][c0 + 1024]; }
            if (tid < 128) nz = zp[c0 * L];
        }
#pragma unroll
        for (int c = 0; c < 8; c++) {
            float4 w1a = *(const float4*)&sW1[c][om];
            float4 w1b = *(const float4*)&sW1[c][om + 4];
            float4 w2a = *(const float4*)&sW2[c][om];
            float4 w2b = *(const float4*)&sW2[c][om + 4];
            float zi = sZi[c][il];
            float4 zj4 = *(const float4*)&sZj[c][jl0];
            float w1v[8] = {w1a.x, w1a.y, w1a.z, w1a.w, w1b.x, w1b.y, w1b.z, w1b.w};
            float w2v[8] = {w2a.x, w2a.y, w2a.z, w2a.w, w2b.x, w2b.y, w2b.z, w2b.w};
            float zj[4] = {zj4.x, zj4.y, zj4.z, zj4.w};
            float dd[4], mm[4];
#pragma unroll
            for (int t = 0; t < 4; t++) {
                dd[t] = fabsf(zi - zj[t]);
                mm[t] = zi * zj[t];
            }
#pragma unroll
            for (int a = 0; a < 8; a++)
#pragma unroll
                for (int t = 0; t < 4; t++)
                    acc[a][t] += w1v[a] * dd[t] + w2v[a] * mm[t];
        }
        if (kk < 127) {
            __syncthreads();
#pragma unroll
            for (int r = 0; r < 4; r++) {
                int t = tid + r * 256;
                sW1[t & 7][t >> 3] = nw1[r];
                sW2[t & 7][t >> 3] = nw2[r];
            }
            if (tid < 64)       sZi[tid >> 3][tid & 7] = nz;
            else if (tid < 128) sZj[(tid - 64) >> 3][tid & 7] = nz;
            __syncthreads();
        }
    }

    int i = i0 + il, jbase = j0 + jl0;
#pragma unroll
    for (int a = 0; a < 8; a++) {
        int o = o0 + om + a;
        float bias = b1[o];
        size_t base = (size_t)o << 16;
#pragma unroll
        for (int t = 0; t < 4; t++) {
            float v = acc[a][t] + bias;
            v = v > 0.f ? v : 0.f;
            int j = jbase + t;
            g_h[base + (i << 8) + j] = v;     // h symmetric: store both halves
            g_h[base + (j << 8) + i] = v;
        }
    }
}

// ---------------- 7x7 conv over 1024 channels, split into 16 channel groups ----------------
// Block: 32x32 output tile (upper-tri tiles only), 64 channels. Sliding-row accumulation.
__global__ __launch_bounds__(256) void k_conv2(const float* __restrict__ w2) {
    int jb = blockIdx.x, ib = blockIdx.y;
    if (jb < ib) return;
    int g = blockIdx.z;
    __shared__ float sT[38][40];
    __shared__ float sKc[49];
    int tid = threadIdx.x;
    int tx = tid & 31, ty = tid >> 5;
    int i0 = ib * 32, j0 = jb * 32;
    int rbase = ty * 4;
    float acc[4] = {0.f, 0.f, 0.f, 0.f};

    for (int c = g * 64; c < g * 64 + 64; c++) {
        __syncthreads();   // previous iteration's readers done before overwrite
        const float* hp = g_h + ((size_t)c << 16);
        for (int t = tid; t < 38 * 38; t += 256) {
            int r = t / 38, cc = t - r * 38;
            int gi = i0 - 3 + r, gj = j0 - 3 + cc;
            float v = 0.f;
            if ((unsigned)gi < 256u && (unsigned)gj < 256u) v = hp[gi * 256 + gj];
            sT[r][cc] = v;
        }
        if (tid < 49) sKc[tid] = w2[c * 49 + tid];
        __syncthreads();
        float wk[49];
#pragma unroll
        for (int q = 0; q < 49; q++) wk[q] = sKc[q];
#pragma unroll
        for (int rr = 0; rr < 10; rr++) {       // 10 h-rows feed 4 output rows
            float seg[7];
#pragma unroll
            for (int b = 0; b < 7; b++) seg[b] = sT[rbase + rr][tx + b];
#pragma unroll
            for (int r = 0; r < 4; r++) {
                int a = rr - r;
                if (a >= 0 && a < 7) {
#pragma unroll
                    for (int b = 0; b < 7; b++)
                        acc[r] += wk[a * 7 + b] * seg[b];
                }
            }
        }
    }
#pragma unroll
    for (int r = 0; r < 4; r++) {
        int i = i0 + rbase + r, j = j0 + tx;
        g_part[g * NPAIR + i * 256 + j] = acc[r];
    }
}

// ---------------- reduce 16 partials + bias, sigmoid, mirror-write maps ----------------
__global__ void k_red(const float* __restrict__ b2, float* __restrict__ out) {
    int idx = blockIdx.x * 256 + threadIdx.x;
    int i = idx >> 8, j = idx & 255;
    if (j < i) return;
    float s = b2[0];
#pragma unroll
    for (int g = 0; g < 16; g++) s += g_part[g * NPAIR + idx];
    float v = 1.f / (1.f + expf(-s));
    out[NEC + i * 256 + j] = v;
    out[NEC + j * 256 + i] = v;
}

extern "C" void kernel_launch(void* const* d_in, const int* in_sizes, int n_in,
                              void* d_out, int out_size) {
    const float* attn    = (const float*)d_in[0];
    const float* pooled  = (const float*)d_in[1];
    const int*   am      = (const int*)d_in[2];
    const float* lin1_w  = (const float*)d_in[3];
    const float* lin1_b  = (const float*)d_in[4];
    const float* cls_w   = (const float*)d_in[5];
    const float* cls_b   = (const float*)d_in[6];
    const float* conv1_w = (const float*)d_in[7];
    const float* conv1_b = (const float*)d_in[8];
    const float* conv2_w = (const float*)d_in[9];
    const float* conv2_b = (const float*)d_in[10];
    float* out = (float*)d_out;

    k_mask<<<1, 256>>>(am);
    k_z<<<256, 256>>>(attn);
    k_lin1<<<128, 256>>>(pooled, lin1_w, lin1_b);
    k_cls<<<250, 256>>>(cls_w, cls_b, out);
    k_h<<<dim3(8, 32, 32), 256>>>(conv1_w, conv1_b);
    k_conv2<<<dim3(8, 8, 16), 256>>>(conv2_w);
    k_red<<<256, 256>>>(conv2_b, out);
}

// round 9
// speedup vs baseline: 1.9996x; 1.9996x over previous
#include <cuda_runtime.h>
#include <cuda_bf16.h>
#include <cstdint>
#include <math.h>

#define L 256
#define C 1024
#define NEC 2000
#define NPAIR 65536

// ---------------- scratch (__device__ globals; no allocations) ----------------
__device__ float g_mask[L];
__device__ float g_z[C * L];                       // z[c][l], masked, transposed
__device__ float g_tmp[C];                         // lin1 output
__device__ float g_h[(size_t)C * NPAIR];           // h[o][i][j]  (268 MB)
__device__ float g_part[16 * NPAIR];               // conv2 channel-group partials
__device__ __nv_bfloat16 g_whi[(size_t)C * 2048];  // W split hi, chunk-interleaved
__device__ __nv_bfloat16 g_wlo[(size_t)C * 2048];  // W split lo

// ---------------- helpers ----------------
__device__ __forceinline__ uint32_t smem_to_u32(const void* p) {
    uint32_t a;
    asm("{ .reg .u64 t; cvta.to.shared.u64 t, %1; cvt.u32.u64 %0, t; }" : "=r"(a) : "l"(p));
    return a;
}
#define CVT_BF16X2(res, a, b) \
    asm("cvt.rn.satfinite.bf16x2.f32 %0, %1, %2;" : "=r"(res) : "f"(b), "f"(a))
#define SWZ128(x) ((x) ^ (((x) >> 3) & 0x70))

__device__ __forceinline__ void ldsm_x4(uint32_t addr, uint32_t* r) {
    asm volatile("ldmatrix.sync.aligned.m8n8.x4.shared.b16 {%0,%1,%2,%3}, [%4];"
                 : "=r"(r[0]), "=r"(r[1]), "=r"(r[2]), "=r"(r[3]) : "r"(addr));
}
__device__ __forceinline__ void mma16816(float* c, const uint32_t* a, uint32_t b0, uint32_t b1) {
    asm volatile(
        "mma.sync.aligned.m16n8k16.row.col.f32.bf16.bf16.f32 "
        "{%0,%1,%2,%3}, {%4,%5,%6,%7}, {%8,%9}, {%0,%1,%2,%3};"
        : "+f"(c[0]), "+f"(c[1]), "+f"(c[2]), "+f"(c[3])
        : "r"(a[0]), "r"(a[1]), "r"(a[2]), "r"(a[3]), "r"(b0), "r"(b1));
}

// SMEM layout (byte offsets from 1024-aligned base)
#define SM_AH 0
#define SM_AL 16384
#define SM_BH 32768
#define SM_BL 65536
#define SM_ZC 98304
#define SMEM_BYTES (98304 + 4352 + 1024)

// ---------------- prep: mask + masked transpose ----------------
__global__ void k_mask(const int* __restrict__ am) {
    __shared__ int red[256];
    int l = threadIdx.x;
    int v = am[l];
    red[l] = v;
    __syncthreads();
    for (int off = 128; off; off >>= 1) {
        if (l < off) red[l] += red[l + off];
        __syncthreads();
    }
    int s = red[0];
    float m = (float)v;
    if (l == 0 || l == s) m = 0.f;
    g_mask[l] = m;
}

__global__ void k_z(const float* __restrict__ attn) {
    int l = blockIdx.x;
    float m = g_mask[l];
    for (int c = threadIdx.x; c < C; c += blockDim.x)
        g_z[c * L + l] = attn[l * C + c] * m;
}

// ---------------- W hi/lo split, chunk-interleaved layout ----------------
// g_w*[o][kc*64+kk]: kk<32 -> W[o][kc*32+kk] (diff half), kk>=32 -> W[o][1024+kc*32+kk-32] (mul half)
__global__ void k_wsplit(const float* __restrict__ W) {
    int idx = blockIdx.x * 256 + threadIdx.x;
    int o = idx >> 11;
    int k = idx & 2047;
    int kc = k >> 6, kk = k & 63;
    int c = (kk < 32) ? (kc * 32 + kk) : (1024 + kc * 32 + kk - 32);
    float v = W[(size_t)o * 2048 + c];
    __nv_bfloat16 hi = __float2bfloat16_rn(v);
    g_whi[idx] = hi;
    g_wlo[idx] = __float2bfloat16_rn(v - __bfloat162float(hi));
}

// ---------------- logits head ----------------
__global__ void k_lin1(const float* __restrict__ pooled, const float* __restrict__ w,
                       const float* __restrict__ b) {
    int gw = (blockIdx.x * blockDim.x + threadIdx.x) >> 5;
    int lane = threadIdx.x & 31;
    if (gw >= C) return;
    const float* row = w + (size_t)gw * C;
    float s = 0.f;
    for (int c2 = lane; c2 < C; c2 += 32) s += row[c2] * pooled[c2];
#pragma unroll
    for (int off = 16; off; off >>= 1) s += __shfl_xor_sync(0xffffffffu, s, off);
    if (lane == 0) g_tmp[gw] = s + b[gw];
}

__global__ void k_cls(const float* __restrict__ w, const float* __restrict__ b,
                      float* __restrict__ out) {
    int gw = (blockIdx.x * blockDim.x + threadIdx.x) >> 5;
    int lane = threadIdx.x & 31;
    if (gw >= NEC) return;
    const float* row = w + (size_t)gw * C;
    float s = 0.f;
    for (int c2 = lane; c2 < C; c2 += 32) s += row[c2] * g_tmp[c2];
#pragma unroll
    for (int off = 16; off; off >>= 1) s += __shfl_xor_sync(0xffffffffu, s, off);
    if (lane == 0) out[gw] = s + b[gw];
}

// ---------------- main GEMM via mma.sync (HMMA), 3xBF16 split ----------------
// CTA: 128 outputs x 256 pairs (16i x 16j, upper-tri blocks). 8 warps = 2(M) x 4(N),
// warp tile 64x64. K=2048 in 32 chunks of 64 (32 ch x {diff,mul}).
__global__ void __launch_bounds__(256, 1) k_hmma(const float* __restrict__ b1) {
    int ib = blockIdx.y, jb = blockIdx.z;
    if (jb < ib) return;
    int m0 = blockIdx.x * 128;
    int i0 = ib * 16, j0 = jb * 16;

    extern __shared__ char smem_raw[];
    char* sm = (char*)(((uintptr_t)smem_raw + 1023) & ~(uintptr_t)1023);
    uint32_t sb = smem_to_u32(sm);
    float* zc = (float*)(sm + SM_ZC);          // [32 ch][33]: cols 0-15 = zi, 16-31 = zj

    int tid = threadIdx.x, wid = tid >> 5, lane = tid & 31;
    int wm = wid >> 2, wn = wid & 3;

    // ldmatrix per-lane address components (non-trans for both A and B)
    int arow = lane & 15, aseg = lane >> 4;                       // A: m16k16 x4
    int brow = (lane & 7) + ((lane >> 4) << 3);                   // B: lanes->n rows
    int bhalf = (lane >> 3) & 1;                                  // k-halves

    int ii = tid >> 4, jj = tid & 15;          // feat-gen pair for this thread (row p=tid)

    float acc[4][8][4];
#pragma unroll
    for (int a = 0; a < 4; a++)
#pragma unroll
        for (int b = 0; b < 8; b++)
#pragma unroll
            for (int r = 0; r < 4; r++) acc[a][b][r] = 0.f;

    for (int kc = 0; kc < 32; kc++) {
        int c0 = kc * 32;
        __syncthreads();   // previous chunk's ldmatrix reads complete

        // ---- load z cache + W tiles ----
#pragma unroll
        for (int r = 0; r < 4; r++) {
            int id2 = tid + r * 256;
            int ch = id2 >> 5, l2 = id2 & 31;
            float v = (l2 < 16) ? g_z[(c0 + ch) * L + i0 + l2]
                                : g_z[(c0 + ch) * L + j0 + (l2 - 16)];
            zc[ch * 33 + l2] = v;
        }
#pragma unroll
        for (int r = 0; r < 4; r++) {
            int q = tid + r * 256;             // 1024 x 16B segments of W tile
            int row = q >> 3, seg = q & 7;
            uint32_t swo = SWZ128((uint32_t)(row * 128 + seg * 16));
            const char* srch = (const char*)(g_whi + (size_t)(m0 + row) * 2048 + kc * 64) + seg * 16;
            const char* srcl = (const char*)(g_wlo + (size_t)(m0 + row) * 2048 + kc * 64) + seg * 16;
            *(float4*)(sm + SM_AH + swo) = *(const float4*)srch;
            *(float4*)(sm + SM_AL + swo) = *(const float4*)srcl;
        }
        __syncthreads();

        // ---- generate feat tile (row = pair tid): 64 bf16 (32 diff | 32 mul), hi+lo ----
        const float* zi = zc + ii;
        const float* zj = zc + 16 + jj;
#pragma unroll
        for (int g = 0; g < 4; g++) {
            uint32_t dh[4], dl[4], mh[4], ml[4];
#pragma unroll
            for (int u = 0; u < 4; u++) {
                int ch = g * 8 + u * 2;
                float a0 = zi[ch * 33], a1 = zi[(ch + 1) * 33];
                float b0 = zj[ch * 33], b1v = zj[(ch + 1) * 33];
                float d0 = fabsf(a0 - b0), d1 = fabsf(a1 - b1v);
                float p0 = a0 * b0, p1 = a1 * b1v;
                uint32_t rh; CVT_BF16X2(rh, d0, d1);
                float h0 = __uint_as_float(rh << 16);
                float h1 = __uint_as_float(rh & 0xffff0000u);
                uint32_t rl; CVT_BF16X2(rl, d0 - h0, d1 - h1);
                uint32_t qh; CVT_BF16X2(qh, p0, p1);
                float q0 = __uint_as_float(qh << 16);
                float q1 = __uint_as_float(qh & 0xffff0000u);
                uint32_t ql; CVT_BF16X2(ql, p0 - q0, p1 - q1);
                dh[u] = rh; dl[u] = rl; mh[u] = qh; ml[u] = ql;
            }
            uint32_t bod = SWZ128((uint32_t)(tid * 128 + g * 16));
            uint32_t bom = SWZ128((uint32_t)(tid * 128 + 64 + g * 16));
            *(uint4*)(sm + SM_BH + bod) = make_uint4(dh[0], dh[1], dh[2], dh[3]);
            *(uint4*)(sm + SM_BL + bod) = make_uint4(dl[0], dl[1], dl[2], dl[3]);
            *(uint4*)(sm + SM_BH + bom) = make_uint4(mh[0], mh[1], mh[2], mh[3]);
            *(uint4*)(sm + SM_BL + bom) = make_uint4(ml[0], ml[1], ml[2], ml[3]);
        }
        __syncthreads();

        // ---- MMA over this chunk: 4 ksteps x 3 passes (hi*hi, hi*lo, lo*hi) ----
#pragma unroll
        for (int ks = 0; ks < 4; ks++) {
            int kb = ks * 32;
            uint32_t af[4][4], bb[4][4];
            // A-hi frags (4 m16 tiles) — stay live through passes 1 and 2
#pragma unroll
            for (int am = 0; am < 4; am++) {
                uint32_t off = SWZ128((uint32_t)((wm * 64 + am * 16 + arow) * 128 + kb + aseg * 16));
                ldsm_x4(sb + SM_AH + off, af[am]);
            }
            // B-hi frags (non-trans: B stored [n][k], k contiguous)
#pragma unroll
            for (int bq = 0; bq < 4; bq++) {
                uint32_t off = SWZ128((uint32_t)((wn * 64 + bq * 16 + brow) * 128 + kb + bhalf * 16));
                ldsm_x4(sb + SM_BH + off, bb[bq]);
            }
            // hi * hi
#pragma unroll
            for (int am = 0; am < 4; am++)
#pragma unroll
                for (int bq = 0; bq < 4; bq++) {
                    mma16816(acc[am][2 * bq], af[am], bb[bq][0], bb[bq][1]);
                    mma16816(acc[am][2 * bq + 1], af[am], bb[bq][2], bb[bq][3]);
                }
            // hi(A) * lo(B): load B-lo into bb, A-hi still live
#pragma unroll
            for (int bq = 0; bq < 4; bq++) {
                uint32_t off = SWZ128((uint32_t)((wn * 64 + bq * 16 + brow) * 128 + kb + bhalf * 16));
                ldsm_x4(sb + SM_BL + off, bb[bq]);
            }
#pragma unroll
            for (int am = 0; am < 4; am++)
#pragma unroll
                for (int bq = 0; bq < 4; bq++) {
                    mma16816(acc[am][2 * bq], af[am], bb[bq][0], bb[bq][1]);
                    mma16816(acc[am][2 * bq + 1], af[am], bb[bq][2], bb[bq][3]);
                }
            // lo(A) * hi(B): replace af with A-lo, reload B-hi into bb
#pragma unroll
            for (int am = 0; am < 4; am++) {
                uint32_t off = SWZ128((uint32_t)((wm * 64 + am * 16 + arow) * 128 + kb + aseg * 16));
                ldsm_x4(sb + SM_AL + off, af[am]);
            }
#pragma unroll
            for (int bq = 0; bq < 4; bq++) {
                uint32_t off = SWZ128((uint32_t)((wn * 64 + bq * 16 + brow) * 128 + kb + bhalf * 16));
                ldsm_x4(sb + SM_BH + off, bb[bq]);
            }
#pragma unroll
            for (int am = 0; am < 4; am++)
#pragma unroll
                for (int bq = 0; bq < 4; bq++) {
                    mma16816(acc[am][2 * bq], af[am], bb[bq][0], bb[bq][1]);
                    mma16816(acc[am][2 * bq + 1], af[am], bb[bq][2], bb[bq][3]);
                }
        }
    }

    // ---- epilogue: bias + relu, mirrored scattered store ----
    int qrow = lane >> 2, qcol = (lane & 3) * 2;
#pragma unroll
    for (int am = 0; am < 4; am++) {
        int mb = wm * 64 + am * 16;
        float bias0 = b1[m0 + mb + qrow];
        float bias1 = b1[m0 + mb + qrow + 8];
#pragma unroll
        for (int bn = 0; bn < 8; bn++) {
            int n = wn * 64 + bn * 8 + qcol;
#pragma unroll
            for (int r = 0; r < 4; r++) {
                int mrow = mb + qrow + (r >> 1) * 8;
                int nn = n + (r & 1);
                float v = acc[am][bn][r] + ((r >> 1) ? bias1 : bias0);
                v = fmaxf(v, 0.f);
                int pi = i0 + (nn >> 4), pj = j0 + (nn & 15);
                float* hp = g_h + ((size_t)(m0 + mrow) << 16);
                hp[pi * 256 + pj] = v;
                hp[pj * 256 + pi] = v;
            }
        }
    }
}

// ---------------- 7x7 conv, 16 channel groups, upper-tri 32x32 tiles ----------------
__global__ __launch_bounds__(256) void k_conv2(const float* __restrict__ w2) {
    int jb = blockIdx.x, ib = blockIdx.y;
    if (jb < ib) return;
    int g = blockIdx.z;
    __shared__ float sT[38][40];
    __shared__ float sKc[49];
    int tid = threadIdx.x;
    int tx = tid & 31, ty = tid >> 5;
    int i0 = ib * 32, j0 = jb * 32;
    int rbase = ty * 4;
    float acc[4] = {0.f, 0.f, 0.f, 0.f};

    for (int c = g * 64; c < g * 64 + 64; c++) {
        __syncthreads();
        const float* hp = g_h + ((size_t)c << 16);
        for (int t = tid; t < 38 * 38; t += 256) {
            int r = t / 38, cc = t - r * 38;
            int gi = i0 - 3 + r, gj = j0 - 3 + cc;
            float v = 0.f;
            if ((unsigned)gi < 256u && (unsigned)gj < 256u) v = hp[gi * 256 + gj];
            sT[r][cc] = v;
        }
        if (tid < 49) sKc[tid] = w2[c * 49 + tid];
        __syncthreads();
        float wk[49];
#pragma unroll
        for (int q = 0; q < 49; q++) wk[q] = sKc[q];
#pragma unroll
        for (int rr = 0; rr < 10; rr++) {
            float seg[7];
#pragma unroll
            for (int b = 0; b < 7; b++) seg[b] = sT[rbase + rr][tx + b];
#pragma unroll
            for (int r = 0; r < 4; r++) {
                int a = rr - r;
                if (a >= 0 && a < 7) {
#pragma unroll
                    for (int b = 0; b < 7; b++)
                        acc[r] += wk[a * 7 + b] * seg[b];
                }
            }
        }
    }
#pragma unroll
    for (int r = 0; r < 4; r++) {
        int i = i0 + rbase + r, j = j0 + tx;
        g_part[g * NPAIR + i * 256 + j] = acc[r];
    }
}

__global__ void k_red(const float* __restrict__ b2, float* __restrict__ out) {
    int idx = blockIdx.x * 256 + threadIdx.x;
    int i = idx >> 8, j = idx & 255;
    if (j < i) return;
    float s = b2[0];
#pragma unroll
    for (int g = 0; g < 16; g++) s += g_part[g * NPAIR + idx];
    float v = 1.f / (1.f + expf(-s));
    out[NEC + i * 256 + j] = v;
    out[NEC + j * 256 + i] = v;
}

extern "C" void kernel_launch(void* const* d_in, const int* in_sizes, int n_in,
                              void* d_out, int out_size) {
    const float* attn    = (const float*)d_in[0];
    const float* pooled  = (const float*)d_in[1];
    const int*   am      = (const int*)d_in[2];
    const float* lin1_w  = (const float*)d_in[3];
    const float* lin1_b  = (const float*)d_in[4];
    const float* cls_w   = (const float*)d_in[5];
    const float* cls_b   = (const float*)d_in[6];
    const float* conv1_w = (const float*)d_in[7];
    const float* conv1_b = (const float*)d_in[8];
    const float* conv2_w = (const float*)d_in[9];
    const float* conv2_b = (const float*)d_in[10];
    float* out = (float*)d_out;

    cudaFuncSetAttribute(k_hmma, cudaFuncAttributeMaxDynamicSharedMemorySize, SMEM_BYTES);

    k_mask<<<1, 256>>>(am);
    k_z<<<256, 256>>>(attn);
    k_wsplit<<<8192, 256>>>(conv1_w);
    k_lin1<<<128, 256>>>(pooled, lin1_w, lin1_b);
    k_cls<<<250, 256>>>(cls_w, cls_b, out);
    k_hmma<<<dim3(8, 16, 16), 256, SMEM_BYTES>>>(conv1_b);
    k_conv2<<<dim3(8, 8, 16), 256>>>(conv2_w);
    k_red<<<256, 256>>>(conv2_b, out);
}

// round 10
// speedup vs baseline: 2.3834x; 1.1920x over previous
#include <cuda_runtime.h>
#include <cuda_bf16.h>
#include <cstdint>
#include <math.h>

#define L 256
#define C 1024
#define NEC 2000
#define NPAIR 65536

// ---------------- scratch (__device__ globals; no allocations) ----------------
__device__ float g_mask[L];
__device__ float g_z[C * L];                       // z[c][l], masked, transposed
__device__ float g_tmp[C];                         // lin1 output
__device__ float g_h[(size_t)C * NPAIR];           // h[o][i][j]  (268 MB)
__device__ float g_part[16 * NPAIR];               // conv2 channel-group partials
__device__ __nv_bfloat16 g_whi[(size_t)C * 2048];  // W split hi, chunk-interleaved
__device__ __nv_bfloat16 g_wlo[(size_t)C * 2048];  // W split lo

// ---------------- helpers ----------------
__device__ __forceinline__ uint32_t smem_to_u32(const void* p) {
    uint32_t a;
    asm("{ .reg .u64 t; cvta.to.shared.u64 t, %1; cvt.u32.u64 %0, t; }" : "=r"(a) : "l"(p));
    return a;
}
#define CVT_BF16X2(res, a, b) \
    asm("cvt.rn.satfinite.bf16x2.f32 %0, %1, %2;" : "=r"(res) : "f"(b), "f"(a))
#define SWZ128(x) ((x) ^ (((x) >> 3) & 0x70))

__device__ __forceinline__ void ldsm_x4(uint32_t addr, uint32_t* r) {
    asm volatile("ldmatrix.sync.aligned.m8n8.x4.shared.b16 {%0,%1,%2,%3}, [%4];"
                 : "=r"(r[0]), "=r"(r[1]), "=r"(r[2]), "=r"(r[3]) : "r"(addr));
}
__device__ __forceinline__ void mma16816(float* c, const uint32_t* a, uint32_t b0, uint32_t b1) {
    asm volatile(
        "mma.sync.aligned.m16n8k16.row.col.f32.bf16.bf16.f32 "
        "{%0,%1,%2,%3}, {%4,%5,%6,%7}, {%8,%9}, {%0,%1,%2,%3};"
        : "+f"(c[0]), "+f"(c[1]), "+f"(c[2]), "+f"(c[3])
        : "r"(a[0]), "r"(a[1]), "r"(a[2]), "r"(a[3]), "r"(b0), "r"(b1));
}

// SMEM layout (byte offsets from 1024-aligned base), double-buffered
#define SB_(s) ((s) * 98304)
#define SM_AH(s) (SB_(s))
#define SM_AL(s) (SB_(s) + 16384)
#define SM_BH(s) (SB_(s) + 32768)
#define SM_BL(s) (SB_(s) + 65536)
#define SM_ZC(s) (196608 + (s) * 4352)
#define SMEM_BYTES (205312 + 1024)

// ---------------- prep: mask + masked transpose ----------------
__global__ void k_mask(const int* __restrict__ am) {
    __shared__ int red[256];
    int l = threadIdx.x;
    int v = am[l];
    red[l] = v;
    __syncthreads();
    for (int off = 128; off; off >>= 1) {
        if (l < off) red[l] += red[l + off];
        __syncthreads();
    }
    int s = red[0];
    float m = (float)v;
    if (l == 0 || l == s) m = 0.f;
    g_mask[l] = m;
}

__global__ void k_z(const float* __restrict__ attn) {
    int l = blockIdx.x;
    float m = g_mask[l];
    for (int c = threadIdx.x; c < C; c += blockDim.x)
        g_z[c * L + l] = attn[l * C + c] * m;
}

// ---------------- W hi/lo split, chunk-interleaved layout ----------------
__global__ void k_wsplit(const float* __restrict__ W) {
    int idx = blockIdx.x * 256 + threadIdx.x;
    int o = idx >> 11;
    int k = idx & 2047;
    int kc = k >> 6, kk = k & 63;
    int c = (kk < 32) ? (kc * 32 + kk) : (1024 + kc * 32 + kk - 32);
    float v = W[(size_t)o * 2048 + c];
    __nv_bfloat16 hi = __float2bfloat16_rn(v);
    g_whi[idx] = hi;
    g_wlo[idx] = __float2bfloat16_rn(v - __bfloat162float(hi));
}

// ---------------- logits head ----------------
__global__ void k_lin1(const float* __restrict__ pooled, const float* __restrict__ w,
                       const float* __restrict__ b) {
    int gw = (blockIdx.x * blockDim.x + threadIdx.x) >> 5;
    int lane = threadIdx.x & 31;
    if (gw >= C) return;
    const float* row = w + (size_t)gw * C;
    float s = 0.f;
    for (int c2 = lane; c2 < C; c2 += 32) s += row[c2] * pooled[c2];
#pragma unroll
    for (int off = 16; off; off >>= 1) s += __shfl_xor_sync(0xffffffffu, s, off);
    if (lane == 0) g_tmp[gw] = s + b[gw];
}

__global__ void k_cls(const float* __restrict__ w, const float* __restrict__ b,
                      float* __restrict__ out) {
    int gw = (blockIdx.x * blockDim.x + threadIdx.x) >> 5;
    int lane = threadIdx.x & 31;
    if (gw >= NEC) return;
    const float* row = w + (size_t)gw * C;
    float s = 0.f;
    for (int c2 = lane; c2 < C; c2 += 32) s += row[c2] * g_tmp[c2];
#pragma unroll
    for (int off = 16; off; off >>= 1) s += __shfl_xor_sync(0xffffffffu, s, off);
    if (lane == 0) out[gw] = s + b[gw];
}

// ---------------- main GEMM via mma.sync, 3xBF16 split, double-buffered pipeline ----------------
__global__ void __launch_bounds__(256, 1) k_hmma(const float* __restrict__ b1) {
    int ib = blockIdx.y, jb = blockIdx.z;
    if (jb < ib) return;
    int m0 = blockIdx.x * 128;
    int i0 = ib * 16, j0 = jb * 16;

    extern __shared__ char smem_raw[];
    char* sm = (char*)(((uintptr_t)smem_raw + 1023) & ~(uintptr_t)1023);
    uint32_t sb = smem_to_u32(sm);

    int tid = threadIdx.x, wid = tid >> 5, lane = tid & 31;
    int wm = wid >> 2, wn = wid & 3;
    int arow = lane & 15, aseg = lane >> 4;
    int brow = (lane & 7) + ((lane >> 4) << 3);
    int bhalf = (lane >> 3) & 1;
    int ii = tid >> 4, jj = tid & 15;

    float acc[4][8][4];
#pragma unroll
    for (int a = 0; a < 4; a++)
#pragma unroll
        for (int b = 0; b < 8; b++)
#pragma unroll
            for (int r = 0; r < 4; r++) acc[a][b][r] = 0.f;

    float pz[4];
    float4 pwh[4], pwl[4];

    // global -> regs for chunk kc
    auto ldgc = [&](int kc) {
        int c0 = kc * 32;
#pragma unroll
        for (int r = 0; r < 4; r++) {
            int id2 = tid + r * 256;
            int ch = id2 >> 5, l2 = id2 & 31;
            pz[r] = (l2 < 16) ? g_z[(c0 + ch) * L + i0 + l2]
                              : g_z[(c0 + ch) * L + j0 + (l2 - 16)];
        }
#pragma unroll
        for (int r = 0; r < 4; r++) {
            int q = tid + r * 256;
            int row = q >> 3, seg = q & 7;
            pwh[r] = *(const float4*)((const char*)(g_whi + (size_t)(m0 + row) * 2048 + kc * 64) + seg * 16);
            pwl[r] = *(const float4*)((const char*)(g_wlo + (size_t)(m0 + row) * 2048 + kc * 64) + seg * 16);
        }
    };
    // regs -> smem stage st (z cache + W tiles)
    auto storec = [&](int st) {
        float* zcs = (float*)(sm + SM_ZC(st));
#pragma unroll
        for (int r = 0; r < 4; r++) {
            int id2 = tid + r * 256;
            int ch = id2 >> 5, l2 = id2 & 31;
            zcs[ch * 33 + l2] = pz[r];
        }
#pragma unroll
        for (int r = 0; r < 4; r++) {
            int q = tid + r * 256;
            int row = q >> 3, seg = q & 7;
            uint32_t swo = SWZ128((uint32_t)(row * 128 + seg * 16));
            *(float4*)(sm + SM_AH(st) + swo) = pwh[r];
            *(float4*)(sm + SM_AL(st) + swo) = pwl[r];
        }
    };
    // feat hi/lo generation into stage st
    auto genf = [&](int st) {
        const float* zi = (const float*)(sm + SM_ZC(st)) + ii;
        const float* zj = (const float*)(sm + SM_ZC(st)) + 16 + jj;
#pragma unroll
        for (int g = 0; g < 4; g++) {
            uint32_t dh[4], dl[4], mh[4], ml[4];
#pragma unroll
            for (int u = 0; u < 4; u++) {
                int ch = g * 8 + u * 2;
                float a0 = zi[ch * 33], a1 = zi[(ch + 1) * 33];
                float b0 = zj[ch * 33], b1v = zj[(ch + 1) * 33];
                float d0 = fabsf(a0 - b0), d1 = fabsf(a1 - b1v);
                float p0 = a0 * b0, p1 = a1 * b1v;
                uint32_t rh; CVT_BF16X2(rh, d0, d1);
                float h0 = __uint_as_float(rh << 16);
                float h1 = __uint_as_float(rh & 0xffff0000u);
                uint32_t rl; CVT_BF16X2(rl, d0 - h0, d1 - h1);
                uint32_t qh; CVT_BF16X2(qh, p0, p1);
                float q0 = __uint_as_float(qh << 16);
                float q1 = __uint_as_float(qh & 0xffff0000u);
                uint32_t ql; CVT_BF16X2(ql, p0 - q0, p1 - q1);
                dh[u] = rh; dl[u] = rl; mh[u] = qh; ml[u] = ql;
            }
            uint32_t bod = SWZ128((uint32_t)(tid * 128 + g * 16));
            uint32_t bom = SWZ128((uint32_t)(tid * 128 + 64 + g * 16));
            *(uint4*)(sm + SM_BH(st) + bod) = make_uint4(dh[0], dh[1], dh[2], dh[3]);
            *(uint4*)(sm + SM_BL(st) + bod) = make_uint4(dl[0], dl[1], dl[2], dl[3]);
            *(uint4*)(sm + SM_BH(st) + bom) = make_uint4(mh[0], mh[1], mh[2], mh[3]);
            *(uint4*)(sm + SM_BL(st) + bom) = make_uint4(ml[0], ml[1], ml[2], ml[3]);
        }
    };
    // one kstep: 3 passes, B-hi and B-lo both held live (16 LDSM)
    auto mmastep = [&](int st, int ks) {
        int kb = ks * 32;
        uint32_t af[4][4], bh[4][4], bl[4][4];
#pragma unroll
        for (int am = 0; am < 4; am++) {
            uint32_t off = SWZ128((uint32_t)((wm * 64 + am * 16 + arow) * 128 + kb + aseg * 16));
            ldsm_x4(sb + SM_AH(st) + off, af[am]);
        }
#pragma unroll
        for (int bq = 0; bq < 4; bq++) {
            uint32_t off = SWZ128((uint32_t)((wn * 64 + bq * 16 + brow) * 128 + kb + bhalf * 16));
            ldsm_x4(sb + SM_BH(st) + off, bh[bq]);
            ldsm_x4(sb + SM_BL(st) + off, bl[bq]);
        }
        // hi * hi
#pragma unroll
        for (int am = 0; am < 4; am++)
#pragma unroll
            for (int bq = 0; bq < 4; bq++) {
                mma16816(acc[am][2 * bq], af[am], bh[bq][0], bh[bq][1]);
                mma16816(acc[am][2 * bq + 1], af[am], bh[bq][2], bh[bq][3]);
            }
        // hi(A) * lo(B)
#pragma unroll
        for (int am = 0; am < 4; am++)
#pragma unroll
            for (int bq = 0; bq < 4; bq++) {
                mma16816(acc[am][2 * bq], af[am], bl[bq][0], bl[bq][1]);
                mma16816(acc[am][2 * bq + 1], af[am], bl[bq][2], bl[bq][3]);
            }
        // lo(A) * hi(B)
#pragma unroll
        for (int am = 0; am < 4; am++) {
            uint32_t off = SWZ128((uint32_t)((wm * 64 + am * 16 + arow) * 128 + kb + aseg * 16));
            ldsm_x4(sb + SM_AL(st) + off, af[am]);
        }
#pragma unroll
        for (int am = 0; am < 4; am++)
#pragma unroll
            for (int bq = 0; bq < 4; bq++) {
                mma16816(acc[am][2 * bq], af[am], bh[bq][0], bh[bq][1]);
                mma16816(acc[am][2 * bq + 1], af[am], bh[bq][2], bh[bq][3]);
            }
    };

    // prologue: fill stage 0 with chunk 0
    ldgc(0);
    storec(0);
    __syncthreads();
    genf(0);

    for (int kc = 0; kc < 32; kc++) {
        int s = kc & 1, ns = s ^ 1;
        bool have = (kc < 31);
        if (have) ldgc(kc + 1);        // global loads in flight across the barrier
        __syncthreads();               // B(s) gen complete; stage-ns buffers free
        if (have) storec(ns);          // z/W(kc+1) -> smem while MMA(kc) runs
        mmastep(s, 0);
        mmastep(s, 1);
        if (have) {
            __syncthreads();           // zc(ns) visible to all for gen
            genf(ns);                  // overlaps tensor-pipe drain of ksteps 0-1
        }
        mmastep(s, 2);
        mmastep(s, 3);
    }

    // ---- epilogue: bias + relu, mirrored scattered store ----
    int qrow = lane >> 2, qcol = (lane & 3) * 2;
#pragma unroll
    for (int am = 0; am < 4; am++) {
        int mb = wm * 64 + am * 16;
        float bias0 = b1[m0 + mb + qrow];
        float bias1 = b1[m0 + mb + qrow + 8];
#pragma unroll
        for (int bn = 0; bn < 8; bn++) {
            int n = wn * 64 + bn * 8 + qcol;
#pragma unroll
            for (int r = 0; r < 4; r++) {
                int mrow = mb + qrow + (r >> 1) * 8;
                int nn = n + (r & 1);
                float v = acc[am][bn][r] + ((r >> 1) ? bias1 : bias0);
                v = fmaxf(v, 0.f);
                int pi = i0 + (nn >> 4), pj = j0 + (nn & 15);
                float* hp = g_h + ((size_t)(m0 + mrow) << 16);
                hp[pi * 256 + pj] = v;
                hp[pj * 256 + pi] = v;
            }
        }
    }
}

// ---------------- 7x7 conv, 16 channel groups, upper-tri 32x32 tiles ----------------
__global__ __launch_bounds__(256) void k_conv2(const float* __restrict__ w2) {
    int jb = blockIdx.x, ib = blockIdx.y;
    if (jb < ib) return;
    int g = blockIdx.z;
    __shared__ float sT[38][40];
    __shared__ float sKc[49];
    int tid = threadIdx.x;
    int tx = tid & 31, ty = tid >> 5;
    int i0 = ib * 32, j0 = jb * 32;
    int rbase = ty * 4;
    float acc[4] = {0.f, 0.f, 0.f, 0.f};

    for (int c = g * 64; c < g * 64 + 64; c++) {
        __syncthreads();
        const float* hp = g_h + ((size_t)c << 16);
        for (int t = tid; t < 38 * 38; t += 256) {
            int r = t / 38, cc = t - r * 38;
            int gi = i0 - 3 + r, gj = j0 - 3 + cc;
            float v = 0.f;
            if ((unsigned)gi < 256u && (unsigned)gj < 256u) v = hp[gi * 256 + gj];
            sT[r][cc] = v;
        }
        if (tid < 49) sKc[tid] = w2[c * 49 + tid];
        __syncthreads();
        float wk[49];
#pragma unroll
        for (int q = 0; q < 49; q++) wk[q] = sKc[q];
#pragma unroll
        for (int rr = 0; rr < 10; rr++) {
            float seg[7];
#pragma unroll
            for (int b = 0; b < 7; b++) seg[b] = sT[rbase + rr][tx + b];
#pragma unroll
            for (int r = 0; r < 4; r++) {
                int a = rr - r;
                if (a >= 0 && a < 7) {
#pragma unroll
                    for (int b = 0; b < 7; b++)
                        acc[r] += wk[a * 7 + b] * seg[b];
                }
            }
        }
    }
#pragma unroll
    for (int r = 0; r < 4; r++) {
        int i = i0 + rbase + r, j = j0 + tx;
        g_part[g * NPAIR + i * 256 + j] = acc[r];
    }
}

__global__ void k_red(const float* __restrict__ b2, float* __restrict__ out) {
    int idx = blockIdx.x * 256 + threadIdx.x;
    int i = idx >> 8, j = idx & 255;
    if (j < i) return;
    float s = b2[0];
#pragma unroll
    for (int g = 0; g < 16; g++) s += g_part[g * NPAIR + idx];
    float v = 1.f / (1.f + expf(-s));
    out[NEC + i * 256 + j] = v;
    out[NEC + j * 256 + i] = v;
}

extern "C" void kernel_launch(void* const* d_in, const int* in_sizes, int n_in,
                              void* d_out, int out_size) {
    const float* attn    = (const float*)d_in[0];
    const float* pooled  = (const float*)d_in[1];
    const int*   am      = (const int*)d_in[2];
    const float* lin1_w  = (const float*)d_in[3];
    const float* lin1_b  = (const float*)d_in[4];
    const float* cls_w   = (const float*)d_in[5];
    const float* cls_b   = (const float*)d_in[6];
    const float* conv1_w = (const float*)d_in[7];
    const float* conv1_b = (const float*)d_in[8];
    const float* conv2_w = (const float*)d_in[9];
    const float* conv2_b = (const float*)d_in[10];
    float* out = (float*)d_out;

    cudaFuncSetAttribute(k_hmma, cudaFuncAttributeMaxDynamicSharedMemorySize, SMEM_BYTES);

    k_mask<<<1, 256>>>(am);
    k_z<<<256, 256>>>(attn);
    k_wsplit<<<8192, 256>>>(conv1_w);
    k_lin1<<<128, 256>>>(pooled, lin1_w, lin1_b);
    k_cls<<<250, 256>>>(cls_w, cls_b, out);
    k_hmma<<<dim3(8, 16, 16), 256, SMEM_BYTES>>>(conv1_b);
    k_conv2<<<dim3(8, 8, 16), 256>>>(conv2_w);
    k_red<<<256, 256>>>(conv2_b, out);
}

// round 11
// speedup vs baseline: 4.7548x; 1.9949x over previous
#include <cuda_runtime.h>
#include <cuda_bf16.h>
#include <cstdint>
#include <math.h>

#define L 256
#define C 1024
#define NEC 2000
#define NPAIR 65536

// ---------------- scratch (__device__ globals; no allocations) ----------------
__device__ float g_mask[L];
__device__ int   g_idx[257];                       // compacted unmasked indices
__device__ int   g_U;                              // count of unmasked positions
__device__ float g_z[C * L];                       // z[c][l], masked, transposed
__device__ float g_tmp[C];                         // lin1 output
__device__ float g_h[(size_t)C * NPAIR];           // h[o][i][j]  (268 MB)
__device__ float g_row[(size_t)C * 257];           // pseudo-pair values: [o][real j], [o][256]=const
__device__ float g_part[16 * NPAIR];               // conv2 channel-group partials
__device__ __nv_bfloat16 g_whi[(size_t)C * 2048];  // W split hi, chunk-interleaved
__device__ __nv_bfloat16 g_wlo[(size_t)C * 2048];  // W split lo

// ---------------- helpers ----------------
__device__ __forceinline__ uint32_t smem_to_u32(const void* p) {
    uint32_t a;
    asm("{ .reg .u64 t; cvta.to.shared.u64 t, %1; cvt.u32.u64 %0, t; }" : "=r"(a) : "l"(p));
    return a;
}
#define CVT_BF16X2(res, a, b) \
    asm("cvt.rn.satfinite.bf16x2.f32 %0, %1, %2;" : "=r"(res) : "f"(b), "f"(a))
#define SWZ128(x) ((x) ^ (((x) >> 3) & 0x70))

__device__ __forceinline__ void ldsm_x4(uint32_t addr, uint32_t* r) {
    asm volatile("ldmatrix.sync.aligned.m8n8.x4.shared.b16 {%0,%1,%2,%3}, [%4];"
                 : "=r"(r[0]), "=r"(r[1]), "=r"(r[2]), "=r"(r[3]) : "r"(addr));
}
__device__ __forceinline__ void mma16816(float* c, const uint32_t* a, uint32_t b0, uint32_t b1) {
    asm volatile(
        "mma.sync.aligned.m16n8k16.row.col.f32.bf16.bf16.f32 "
        "{%0,%1,%2,%3}, {%4,%5,%6,%7}, {%8,%9}, {%0,%1,%2,%3};"
        : "+f"(c[0]), "+f"(c[1]), "+f"(c[2]), "+f"(c[3])
        : "r"(a[0]), "r"(a[1]), "r"(a[2]), "r"(a[3]), "r"(b0), "r"(b1));
}

// SMEM layout (byte offsets from 1024-aligned base), double-buffered
#define SB_(s) ((s) * 98304)
#define SM_AH(s) (SB_(s))
#define SM_AL(s) (SB_(s) + 16384)
#define SM_BH(s) (SB_(s) + 32768)
#define SM_BL(s) (SB_(s) + 65536)
#define SM_ZC(s) (196608 + (s) * 4352)
#define SM_SIX 205312
#define SMEM_BYTES (205312 + 128 + 1024)

// ---------------- prep: mask + compacted index list ----------------
__global__ void k_mask(const int* __restrict__ am) {
    __shared__ int red[256];
    __shared__ int scn[256];
    int l = threadIdx.x;
    int v = am[l];
    red[l] = v;
    __syncthreads();
    for (int off = 128; off; off >>= 1) {
        if (l < off) red[l] += red[l + off];
        __syncthreads();
    }
    int s = red[0];                 // sum of mask; position s gets zeroed (SEP)
    float m = (float)v;
    if (l == 0 || l == s) m = 0.f;  // CLS + SEP masked out
    g_mask[l] = m;
    // deterministic inclusive scan over "unmasked" flags (Hillis-Steele)
    int flag = (m != 0.f) ? 1 : 0;
    scn[l] = flag;
    __syncthreads();
    for (int off = 1; off < 256; off <<= 1) {
        int t = (l >= off) ? scn[l - off] : 0;
        __syncthreads();
        scn[l] += t;
        __syncthreads();
    }
    if (flag) g_idx[scn[l] - 1] = l;
    if (l == 255) g_U = scn[255];
}

__global__ void k_z(const float* __restrict__ attn) {
    int l = blockIdx.x;
    float m = g_mask[l];
    for (int c = threadIdx.x; c < C; c += blockDim.x)
        g_z[c * L + l] = attn[l * C + c] * m;
}

// ---------------- W hi/lo split, chunk-interleaved layout ----------------
__global__ void k_wsplit(const float* __restrict__ W) {
    int idx = blockIdx.x * 256 + threadIdx.x;
    int o = idx >> 11;
    int k = idx & 2047;
    int kc = k >> 6, kk = k & 63;
    int c = (kk < 32) ? (kc * 32 + kk) : (1024 + kc * 32 + kk - 32);
    float v = W[(size_t)o * 2048 + c];
    __nv_bfloat16 hi = __float2bfloat16_rn(v);
    g_whi[idx] = hi;
    g_wlo[idx] = __float2bfloat16_rn(v - __bfloat162float(hi));
}

// ---------------- logits head ----------------
__global__ void k_lin1(const float* __restrict__ pooled, const float* __restrict__ w,
                       const float* __restrict__ b) {
    int gw = (blockIdx.x * blockDim.x + threadIdx.x) >> 5;
    int lane = threadIdx.x & 31;
    if (gw >= C) return;
    const float* row = w + (size_t)gw * C;
    float s = 0.f;
    for (int c2 = lane; c2 < C; c2 += 32) s += row[c2] * pooled[c2];
#pragma unroll
    for (int off = 16; off; off >>= 1) s += __shfl_xor_sync(0xffffffffu, s, off);
    if (lane == 0) g_tmp[gw] = s + b[gw];
}

__global__ void k_cls(const float* __restrict__ w, const float* __restrict__ b,
                      float* __restrict__ out) {
    int gw = (blockIdx.x * blockDim.x + threadIdx.x) >> 5;
    int lane = threadIdx.x & 31;
    if (gw >= NEC) return;
    const float* row = w + (size_t)gw * C;
    float s = 0.f;
    for (int c2 = lane; c2 < C; c2 += 32) s += row[c2] * g_tmp[c2];
#pragma unroll
    for (int off = 16; off; off >>= 1) s += __shfl_xor_sync(0xffffffffu, s, off);
    if (lane == 0) out[gw] = s + b[gw];
}

// ---------------- main GEMM: compacted pairs (unmasked + 1 pseudo), 3xBF16 split ----------------
__global__ void __launch_bounds__(256, 1) k_hmma(const float* __restrict__ b1) {
    int ib = blockIdx.y, jb = blockIdx.z;
    int U = g_U;
    int T = (U + 16) >> 4;            // ceil((U+1)/16): tiles over U real + 1 pseudo
    if (jb < ib || ib >= T || jb >= T) return;
    int m0 = blockIdx.x * 128;
    int i0 = ib * 16, j0 = jb * 16;

    extern __shared__ char smem_raw[];
    char* sm = (char*)(((uintptr_t)smem_raw + 1023) & ~(uintptr_t)1023);
    uint32_t sb = smem_to_u32(sm);
    int* six = (int*)(sm + SM_SIX);   // [0..15]=real idx of i-tile, [16..31]=j-tile, -1=pseudo/pad

    int tid = threadIdx.x, wid = tid >> 5, lane = tid & 31;
    int wm = wid >> 2, wn = wid & 3;
    int arow = lane & 15, aseg = lane >> 4;
    int brow = (lane & 7) + ((lane >> 4) << 3);
    int bhalf = (lane >> 3) & 1;

    if (tid < 32) {
        int a = (tid < 16) ? (i0 + tid) : (j0 + tid - 16);
        six[tid] = (a < U) ? g_idx[a] : -1;
    }
    __syncthreads();

    float acc[4][8][4];
#pragma unroll
    for (int a = 0; a < 4; a++)
#pragma unroll
        for (int b = 0; b < 8; b++)
#pragma unroll
            for (int r = 0; r < 4; r++) acc[a][b][r] = 0.f;

    float pz[4];
    float4 pwh[4], pwl[4];

    auto ldgc = [&](int kc) {
        int c0 = kc * 32;
#pragma unroll
        for (int r = 0; r < 4; r++) {
            int id2 = tid + r * 256;
            int ch = id2 >> 5, l2 = id2 & 31;
            int pos = six[l2];
            pz[r] = (pos >= 0) ? g_z[(c0 + ch) * L + pos] : 0.f;
        }
#pragma unroll
        for (int r = 0; r < 4; r++) {
            int q = tid + r * 256;
            int row = q >> 3, seg = q & 7;
            pwh[r] = *(const float4*)((const char*)(g_whi + (size_t)(m0 + row) * 2048 + kc * 64) + seg * 16);
            pwl[r] = *(const float4*)((const char*)(g_wlo + (size_t)(m0 + row) * 2048 + kc * 64) + seg * 16);
        }
    };
    auto storec = [&](int st) {
        float* zcs = (float*)(sm + SM_ZC(st));
#pragma unroll
        for (int r = 0; r < 4; r++) {
            int id2 = tid + r * 256;
            int ch = id2 >> 5, l2 = id2 & 31;
            zcs[ch * 33 + l2] = pz[r];
        }
#pragma unroll
        for (int r = 0; r < 4; r++) {
            int q = tid + r * 256;
            int row = q >> 3, seg = q & 7;
            uint32_t swo = SWZ128((uint32_t)(row * 128 + seg * 16));
            *(float4*)(sm + SM_AH(st) + swo) = pwh[r];
            *(float4*)(sm + SM_AL(st) + swo) = pwl[r];
        }
    };
    int ii = tid >> 4, jj = tid & 15;
    auto genf = [&](int st) {
        const float* zi = (const float*)(sm + SM_ZC(st)) + ii;
        const float* zj = (const float*)(sm + SM_ZC(st)) + 16 + jj;
#pragma unroll
        for (int g = 0; g < 4; g++) {
            uint32_t dh[4], dl[4], mh[4], ml[4];
#pragma unroll
            for (int u = 0; u < 4; u++) {
                int ch = g * 8 + u * 2;
                float a0 = zi[ch * 33], a1 = zi[(ch + 1) * 33];
                float b0 = zj[ch * 33], b1v = zj[(ch + 1) * 33];
                float d0 = fabsf(a0 - b0), d1 = fabsf(a1 - b1v);
                float p0 = a0 * b0, p1 = a1 * b1v;
                uint32_t rh; CVT_BF16X2(rh, d0, d1);
                float h0 = __uint_as_float(rh << 16);
                float h1 = __uint_as_float(rh & 0xffff0000u);
                uint32_t rl; CVT_BF16X2(rl, d0 - h0, d1 - h1);
                uint32_t qh; CVT_BF16X2(qh, p0, p1);
                float q0 = __uint_as_float(qh << 16);
                float q1 = __uint_as_float(qh & 0xffff0000u);
                uint32_t ql; CVT_BF16X2(ql, p0 - q0, p1 - q1);
                dh[u] = rh; dl[u] = rl; mh[u] = qh; ml[u] = ql;
            }
            uint32_t bod = SWZ128((uint32_t)(tid * 128 + g * 16));
            uint32_t bom = SWZ128((uint32_t)(tid * 128 + 64 + g * 16));
            *(uint4*)(sm + SM_BH(st) + bod) = make_uint4(dh[0], dh[1], dh[2], dh[3]);
            *(uint4*)(sm + SM_BL(st) + bod) = make_uint4(dl[0], dl[1], dl[2], dl[3]);
            *(uint4*)(sm + SM_BH(st) + bom) = make_uint4(mh[0], mh[1], mh[2], mh[3]);
            *(uint4*)(sm + SM_BL(st) + bom) = make_uint4(ml[0], ml[1], ml[2], ml[3]);
        }
    };
    auto mmastep = [&](int st, int ks) {
        int kb = ks * 32;
        uint32_t af[4][4], bh[4][4], bl[4][4];
#pragma unroll
        for (int am = 0; am < 4; am++) {
            uint32_t off = SWZ128((uint32_t)((wm * 64 + am * 16 + arow) * 128 + kb + aseg * 16));
            ldsm_x4(sb + SM_AH(st) + off, af[am]);
        }
#pragma unroll
        for (int bq = 0; bq < 4; bq++) {
            uint32_t off = SWZ128((uint32_t)((wn * 64 + bq * 16 + brow) * 128 + kb + bhalf * 16));
            ldsm_x4(sb + SM_BH(st) + off, bh[bq]);
            ldsm_x4(sb + SM_BL(st) + off, bl[bq]);
        }
#pragma unroll
        for (int am = 0; am < 4; am++)
#pragma unroll
            for (int bq = 0; bq < 4; bq++) {
                mma16816(acc[am][2 * bq], af[am], bh[bq][0], bh[bq][1]);
                mma16816(acc[am][2 * bq + 1], af[am], bh[bq][2], bh[bq][3]);
            }
#pragma unroll
        for (int am = 0; am < 4; am++)
#pragma unroll
            for (int bq = 0; bq < 4; bq++) {
                mma16816(acc[am][2 * bq], af[am], bl[bq][0], bl[bq][1]);
                mma16816(acc[am][2 * bq + 1], af[am], bl[bq][2], bl[bq][3]);
            }
#pragma unroll
        for (int am = 0; am < 4; am++) {
            uint32_t off = SWZ128((uint32_t)((wm * 64 + am * 16 + arow) * 128 + kb + aseg * 16));
            ldsm_x4(sb + SM_AL(st) + off, af[am]);
        }
#pragma unroll
        for (int am = 0; am < 4; am++)
#pragma unroll
            for (int bq = 0; bq < 4; bq++) {
                mma16816(acc[am][2 * bq], af[am], bh[bq][0], bh[bq][1]);
                mma16816(acc[am][2 * bq + 1], af[am], bh[bq][2], bh[bq][3]);
            }
    };

    // prologue
    ldgc(0);
    storec(0);
    __syncthreads();
    genf(0);

    for (int kc = 0; kc < 32; kc++) {
        int s = kc & 1, ns = s ^ 1;
        bool have = (kc < 31);
        if (have) ldgc(kc + 1);
        __syncthreads();
        if (have) storec(ns);
        mmastep(s, 0);
        mmastep(s, 1);
        if (have) {
            __syncthreads();
            genf(ns);
        }
        mmastep(s, 2);
        mmastep(s, 3);
    }

    // ---- epilogue: bias + relu; scatter real pairs to g_h, pseudo pairs to g_row ----
    int qrow = lane >> 2, qcol = (lane & 3) * 2;
#pragma unroll
    for (int am = 0; am < 4; am++) {
        int mb = wm * 64 + am * 16;
        float bias0 = b1[m0 + mb + qrow];
        float bias1 = b1[m0 + mb + qrow + 8];
#pragma unroll
        for (int bn = 0; bn < 8; bn++) {
            int n = wn * 64 + bn * 8 + qcol;
#pragma unroll
            for (int r = 0; r < 4; r++) {
                int mrow = mb + qrow + (r >> 1) * 8;
                int nn = n + (r & 1);
                float v = acc[am][bn][r] + ((r >> 1) ? bias1 : bias0);
                v = fmaxf(v, 0.f);
                int sa = nn >> 4, sj = nn & 15;
                int ri = six[sa], rj = six[16 + sj];
                int o = m0 + mrow;
                if (ri >= 0 && rj >= 0) {
                    float* hp = g_h + ((size_t)o << 16);
                    hp[ri * 256 + rj] = v;
                    hp[rj * 256 + ri] = v;
                } else {
                    int pa = i0 + sa, pb = j0 + sj;
                    if (pa == U && rj >= 0)      g_row[(size_t)o * 257 + rj] = v;
                    else if (pb == U && ri >= 0) g_row[(size_t)o * 257 + ri] = v;
                    else if (pa == U && pb == U) g_row[(size_t)o * 257 + 256] = v;
                }
            }
        }
    }
}

// ---------------- broadcast: fill masked rows/cols of g_h from g_row ----------------
__global__ void k_bcast() {
    int i = blockIdx.x;
    int o = blockIdx.y;
    int j = threadIdx.x;
    bool mi = (g_mask[i] == 0.f);
    bool mj = (g_mask[j] == 0.f);
    if (!mi && !mj) return;           // real pair: written by k_hmma
    const float* rw = g_row + (size_t)o * 257;
    float v = mi ? (mj ? rw[256] : rw[j]) : rw[i];
    g_h[((size_t)o << 16) + i * 256 + j] = v;
}

// ---------------- 7x7 conv, 16 channel groups, upper-tri 32x32 tiles ----------------
__global__ __launch_bounds__(256) void k_conv2(const float* __restrict__ w2) {
    int jb = blockIdx.x, ib = blockIdx.y;
    if (jb < ib) return;
    int g = blockIdx.z;
    __shared__ float sT[38][40];
    __shared__ float sKc[49];
    int tid = threadIdx.x;
    int tx = tid & 31, ty = tid >> 5;
    int i0 = ib * 32, j0 = jb * 32;
    int rbase = ty * 4;
    float acc[4] = {0.f, 0.f, 0.f, 0.f};

    for (int c = g * 64; c < g * 64 + 64; c++) {
        __syncthreads();
        const float* hp = g_h + ((size_t)c << 16);
        for (int t = tid; t < 38 * 38; t += 256) {
            int r = t / 38, cc = t - r * 38;
            int gi = i0 - 3 + r, gj = j0 - 3 + cc;
            float v = 0.f;
            if ((unsigned)gi < 256u && (unsigned)gj < 256u) v = hp[gi * 256 + gj];
            sT[r][cc] = v;
        }
        if (tid < 49) sKc[tid] = w2[c * 49 + tid];
        __syncthreads();
        float wk[49];
#pragma unroll
        for (int q = 0; q < 49; q++) wk[q] = sKc[q];
#pragma unroll
        for (int rr = 0; rr < 10; rr++) {
            float seg[7];
#pragma unroll
            for (int b = 0; b < 7; b++) seg[b] = sT[rbase + rr][tx + b];
#pragma unroll
            for (int r = 0; r < 4; r++) {
                int a = rr - r;
                if (a >= 0 && a < 7) {
#pragma unroll
                    for (int b = 0; b < 7; b++)
                        acc[r] += wk[a * 7 + b] * seg[b];
                }
            }
        }
    }
#pragma unroll
    for (int r = 0; r < 4; r++) {
        int i = i0 + rbase + r, j = j0 + tx;
        g_part[g * NPAIR + i * 256 + j] = acc[r];
    }
}

__global__ void k_red(const float* __restrict__ b2, float* __restrict__ out) {
    int idx = blockIdx.x * 256 + threadIdx.x;
    int i = idx >> 8, j = idx & 255;
    if (j < i) return;
    float s = b2[0];
#pragma unroll
    for (int g = 0; g < 16; g++) s += g_part[g * NPAIR + idx];
    float v = 1.f / (1.f + expf(-s));
    out[NEC + i * 256 + j] = v;
    out[NEC + j * 256 + i] = v;
}

extern "C" void kernel_launch(void* const* d_in, const int* in_sizes, int n_in,
                              void* d_out, int out_size) {
    const float* attn    = (const float*)d_in[0];
    const float* pooled  = (const float*)d_in[1];
    const int*   am      = (const int*)d_in[2];
    const float* lin1_w  = (const float*)d_in[3];
    const float* lin1_b  = (const float*)d_in[4];
    const float* cls_w   = (const float*)d_in[5];
    const float* cls_b   = (const float*)d_in[6];
    const float* conv1_w = (const float*)d_in[7];
    const float* conv1_b = (const float*)d_in[8];
    const float* conv2_w = (const float*)d_in[9];
    const float* conv2_b = (const float*)d_in[10];
    float* out = (float*)d_out;

    cudaFuncSetAttribute(k_hmma, cudaFuncAttributeMaxDynamicSharedMemorySize, SMEM_BYTES);

    k_mask<<<1, 256>>>(am);
    k_z<<<256, 256>>>(attn);
    k_wsplit<<<8192, 256>>>(conv1_w);
    k_lin1<<<128, 256>>>(pooled, lin1_w, lin1_b);
    k_cls<<<250, 256>>>(cls_w, cls_b, out);
    k_hmma<<<dim3(8, 17, 17), 256, SMEM_BYTES>>>(conv1_b);
    k_bcast<<<dim3(256, 1024), 256>>>();
    k_conv2<<<dim3(8, 8, 16), 256>>>(conv2_w);
    k_red<<<256, 256>>>(conv2_b, out);
}

// round 12
// speedup vs baseline: 5.4149x; 1.1388x over previous
#include <cuda_runtime.h>
#include <cuda_bf16.h>
#include <cstdint>
#include <math.h>

#define L 256
#define C 1024
#define NEC 2000
#define NPAIR 65536

// ---------------- scratch (__device__ globals; no allocations) ----------------
__device__ float g_mask[L];
__device__ int   g_idx[257];                       // compacted unmasked indices
__device__ int   g_U;                              // count of unmasked positions
__device__ float g_z[C * L];                       // z[c][l], masked, transposed
__device__ float g_tmp[C];                         // lin1 output
__device__ float g_h[(size_t)C * NPAIR];           // h[o][i][j]  (sparse: real pairs only)
__device__ float g_row[(size_t)C * 257];           // pseudo-pair values: [o][real j], [o][256]=const
__device__ float g_part[16 * NPAIR];               // conv2 channel-group partials
__device__ __nv_bfloat16 g_whi[(size_t)C * 2048];  // W split hi, chunk-interleaved
__device__ __nv_bfloat16 g_wlo[(size_t)C * 2048];  // W split lo

// ---------------- helpers ----------------
__device__ __forceinline__ uint32_t smem_to_u32(const void* p) {
    uint32_t a;
    asm("{ .reg .u64 t; cvta.to.shared.u64 t, %1; cvt.u32.u64 %0, t; }" : "=r"(a) : "l"(p));
    return a;
}
#define CVT_BF16X2(res, a, b) \
    asm("cvt.rn.satfinite.bf16x2.f32 %0, %1, %2;" : "=r"(res) : "f"(b), "f"(a))
#define SWZ128(x) ((x) ^ (((x) >> 3) & 0x70))

__device__ __forceinline__ void ldsm_x4(uint32_t addr, uint32_t* r) {
    asm volatile("ldmatrix.sync.aligned.m8n8.x4.shared.b16 {%0,%1,%2,%3}, [%4];"
                 : "=r"(r[0]), "=r"(r[1]), "=r"(r[2]), "=r"(r[3]) : "r"(addr));
}
__device__ __forceinline__ void mma16816(float* c, const uint32_t* a, uint32_t b0, uint32_t b1) {
    asm volatile(
        "mma.sync.aligned.m16n8k16.row.col.f32.bf16.bf16.f32 "
        "{%0,%1,%2,%3}, {%4,%5,%6,%7}, {%8,%9}, {%0,%1,%2,%3};"
        : "+f"(c[0]), "+f"(c[1]), "+f"(c[2]), "+f"(c[3])
        : "r"(a[0]), "r"(a[1]), "r"(a[2]), "r"(a[3]), "r"(b0), "r"(b1));
}

// SMEM layout (byte offsets from 1024-aligned base), double-buffered
#define SB_(s) ((s) * 98304)
#define SM_AH(s) (SB_(s))
#define SM_AL(s) (SB_(s) + 16384)
#define SM_BH(s) (SB_(s) + 32768)
#define SM_BL(s) (SB_(s) + 65536)
#define SM_ZC(s) (196608 + (s) * 4352)
#define SM_SIX 205312
#define SMEM_BYTES (205312 + 128 + 1024)

// ---------------- prep: mask + compacted index list ----------------
__global__ void k_mask(const int* __restrict__ am) {
    __shared__ int red[256];
    __shared__ int scn[256];
    int l = threadIdx.x;
    int v = am[l];
    red[l] = v;
    __syncthreads();
    for (int off = 128; off; off >>= 1) {
        if (l < off) red[l] += red[l + off];
        __syncthreads();
    }
    int s = red[0];                 // sum of mask; position s gets zeroed (SEP)
    float m = (float)v;
    if (l == 0 || l == s) m = 0.f;  // CLS + SEP masked out
    g_mask[l] = m;
    // deterministic inclusive scan over "unmasked" flags
    int flag = (m != 0.f) ? 1 : 0;
    scn[l] = flag;
    __syncthreads();
    for (int off = 1; off < 256; off <<= 1) {
        int t = (l >= off) ? scn[l - off] : 0;
        __syncthreads();
        scn[l] += t;
        __syncthreads();
    }
    if (flag) g_idx[scn[l] - 1] = l;
    if (l == 255) g_U = scn[255];
}

__global__ void k_z(const float* __restrict__ attn) {
    int l = blockIdx.x;
    float m = g_mask[l];
    for (int c = threadIdx.x; c < C; c += blockDim.x)
        g_z[c * L + l] = attn[l * C + c] * m;
}

// ---------------- W hi/lo split, chunk-interleaved layout ----------------
__global__ void k_wsplit(const float* __restrict__ W) {
    int idx = blockIdx.x * 256 + threadIdx.x;
    int o = idx >> 11;
    int k = idx & 2047;
    int kc = k >> 6, kk = k & 63;
    int c = (kk < 32) ? (kc * 32 + kk) : (1024 + kc * 32 + kk - 32);
    float v = W[(size_t)o * 2048 + c];
    __nv_bfloat16 hi = __float2bfloat16_rn(v);
    g_whi[idx] = hi;
    g_wlo[idx] = __float2bfloat16_rn(v - __bfloat162float(hi));
}

// ---------------- logits head ----------------
__global__ void k_lin1(const float* __restrict__ pooled, const float* __restrict__ w,
                       const float* __restrict__ b) {
    int gw = (blockIdx.x * blockDim.x + threadIdx.x) >> 5;
    int lane = threadIdx.x & 31;
    if (gw >= C) return;
    const float* row = w + (size_t)gw * C;
    float s = 0.f;
    for (int c2 = lane; c2 < C; c2 += 32) s += row[c2] * pooled[c2];
#pragma unroll
    for (int off = 16; off; off >>= 1) s += __shfl_xor_sync(0xffffffffu, s, off);
    if (lane == 0) g_tmp[gw] = s + b[gw];
}

__global__ void k_cls(const float* __restrict__ w, const float* __restrict__ b,
                      float* __restrict__ out) {
    int gw = (blockIdx.x * blockDim.x + threadIdx.x) >> 5;
    int lane = threadIdx.x & 31;
    if (gw >= NEC) return;
    const float* row = w + (size_t)gw * C;
    float s = 0.f;
    for (int c2 = lane; c2 < C; c2 += 32) s += row[c2] * g_tmp[c2];
#pragma unroll
    for (int off = 16; off; off >>= 1) s += __shfl_xor_sync(0xffffffffu, s, off);
    if (lane == 0) out[gw] = s + b[gw];
}

// ---------------- main GEMM: compacted pairs (unmasked + 1 pseudo), 3xBF16 split ----------------
__global__ void __launch_bounds__(256, 1) k_hmma(const float* __restrict__ b1) {
    int ib = blockIdx.y, jb = blockIdx.z;
    int U = g_U;
    int T = (U + 16) >> 4;            // ceil((U+1)/16)
    if (jb < ib || ib >= T || jb >= T) return;
    int m0 = blockIdx.x * 128;
    int i0 = ib * 16, j0 = jb * 16;

    extern __shared__ char smem_raw[];
    char* sm = (char*)(((uintptr_t)smem_raw + 1023) & ~(uintptr_t)1023);
    uint32_t sb = smem_to_u32(sm);
    int* six = (int*)(sm + SM_SIX);   // [0..15]=real idx of i-tile, [16..31]=j-tile, -1=pseudo/pad

    int tid = threadIdx.x, wid = tid >> 5, lane = tid & 31;
    int wm = wid >> 2, wn = wid & 3;
    int arow = lane & 15, aseg = lane >> 4;
    int brow = (lane & 7) + ((lane >> 4) << 3);
    int bhalf = (lane >> 3) & 1;

    if (tid < 32) {
        int a = (tid < 16) ? (i0 + tid) : (j0 + tid - 16);
        six[tid] = (a < U) ? g_idx[a] : -1;
    }
    __syncthreads();

    float acc[4][8][4];
#pragma unroll
    for (int a = 0; a < 4; a++)
#pragma unroll
        for (int b = 0; b < 8; b++)
#pragma unroll
            for (int r = 0; r < 4; r++) acc[a][b][r] = 0.f;

    float pz[4];
    float4 pwh[4], pwl[4];

    auto ldgc = [&](int kc) {
        int c0 = kc * 32;
#pragma unroll
        for (int r = 0; r < 4; r++) {
            int id2 = tid + r * 256;
            int ch = id2 >> 5, l2 = id2 & 31;
            int pos = six[l2];
            pz[r] = (pos >= 0) ? g_z[(c0 + ch) * L + pos] : 0.f;
        }
#pragma unroll
        for (int r = 0; r < 4; r++) {
            int q = tid + r * 256;
            int row = q >> 3, seg = q & 7;
            pwh[r] = *(const float4*)((const char*)(g_whi + (size_t)(m0 + row) * 2048 + kc * 64) + seg * 16);
            pwl[r] = *(const float4*)((const char*)(g_wlo + (size_t)(m0 + row) * 2048 + kc * 64) + seg * 16);
        }
    };
    auto storec = [&](int st) {
        float* zcs = (float*)(sm + SM_ZC(st));
#pragma unroll
        for (int r = 0; r < 4; r++) {
            int id2 = tid + r * 256;
            int ch = id2 >> 5, l2 = id2 & 31;
            zcs[ch * 33 + l2] = pz[r];
        }
#pragma unroll
        for (int r = 0; r < 4; r++) {
            int q = tid + r * 256;
            int row = q >> 3, seg = q & 7;
            uint32_t swo = SWZ128((uint32_t)(row * 128 + seg * 16));
            *(float4*)(sm + SM_AH(st) + swo) = pwh[r];
            *(float4*)(sm + SM_AL(st) + swo) = pwl[r];
        }
    };
    int ii = tid >> 4, jj = tid & 15;
    auto genf = [&](int st) {
        const float* zi = (const float*)(sm + SM_ZC(st)) + ii;
        const float* zj = (const float*)(sm + SM_ZC(st)) + 16 + jj;
#pragma unroll
        for (int g = 0; g < 4; g++) {
            uint32_t dh[4], dl[4], mh[4], ml[4];
#pragma unroll
            for (int u = 0; u < 4; u++) {
                int ch = g * 8 + u * 2;
                float a0 = zi[ch * 33], a1 = zi[(ch + 1) * 33];
                float b0 = zj[ch * 33], b1v = zj[(ch + 1) * 33];
                float d0 = fabsf(a0 - b0), d1 = fabsf(a1 - b1v);
                float p0 = a0 * b0, p1 = a1 * b1v;
                uint32_t rh; CVT_BF16X2(rh, d0, d1);
                float h0 = __uint_as_float(rh << 16);
                float h1 = __uint_as_float(rh & 0xffff0000u);
                uint32_t rl; CVT_BF16X2(rl, d0 - h0, d1 - h1);
                uint32_t qh; CVT_BF16X2(qh, p0, p1);
                float q0 = __uint_as_float(qh << 16);
                float q1 = __uint_as_float(qh & 0xffff0000u);
                uint32_t ql; CVT_BF16X2(ql, p0 - q0, p1 - q1);
                dh[u] = rh; dl[u] = rl; mh[u] = qh; ml[u] = ql;
            }
            uint32_t bod = SWZ128((uint32_t)(tid * 128 + g * 16));
            uint32_t bom = SWZ128((uint32_t)(tid * 128 + 64 + g * 16));
            *(uint4*)(sm + SM_BH(st) + bod) = make_uint4(dh[0], dh[1], dh[2], dh[3]);
            *(uint4*)(sm + SM_BL(st) + bod) = make_uint4(dl[0], dl[1], dl[2], dl[3]);
            *(uint4*)(sm + SM_BH(st) + bom) = make_uint4(mh[0], mh[1], mh[2], mh[3]);
            *(uint4*)(sm + SM_BL(st) + bom) = make_uint4(ml[0], ml[1], ml[2], ml[3]);
        }
    };
    auto mmastep = [&](int st, int ks) {
        int kb = ks * 32;
        uint32_t af[4][4], bh[4][4], bl[4][4];
#pragma unroll
        for (int am = 0; am < 4; am++) {
            uint32_t off = SWZ128((uint32_t)((wm * 64 + am * 16 + arow) * 128 + kb + aseg * 16));
            ldsm_x4(sb + SM_AH(st) + off, af[am]);
        }
#pragma unroll
        for (int bq = 0; bq < 4; bq++) {
            uint32_t off = SWZ128((uint32_t)((wn * 64 + bq * 16 + brow) * 128 + kb + bhalf * 16));
            ldsm_x4(sb + SM_BH(st) + off, bh[bq]);
            ldsm_x4(sb + SM_BL(st) + off, bl[bq]);
        }
#pragma unroll
        for (int am = 0; am < 4; am++)
#pragma unroll
            for (int bq = 0; bq < 4; bq++) {
                mma16816(acc[am][2 * bq], af[am], bh[bq][0], bh[bq][1]);
                mma16816(acc[am][2 * bq + 1], af[am], bh[bq][2], bh[bq][3]);
            }
#pragma unroll
        for (int am = 0; am < 4; am++)
#pragma unroll
            for (int bq = 0; bq < 4; bq++) {
                mma16816(acc[am][2 * bq], af[am], bl[bq][0], bl[bq][1]);
                mma16816(acc[am][2 * bq + 1], af[am], bl[bq][2], bl[bq][3]);
            }
#pragma unroll
        for (int am = 0; am < 4; am++) {
            uint32_t off = SWZ128((uint32_t)((wm * 64 + am * 16 + arow) * 128 + kb + aseg * 16));
            ldsm_x4(sb + SM_AL(st) + off, af[am]);
        }
#pragma unroll
        for (int am = 0; am < 4; am++)
#pragma unroll
            for (int bq = 0; bq < 4; bq++) {
                mma16816(acc[am][2 * bq], af[am], bh[bq][0], bh[bq][1]);
                mma16816(acc[am][2 * bq + 1], af[am], bh[bq][2], bh[bq][3]);
            }
    };

    // prologue
    ldgc(0);
    storec(0);
    __syncthreads();
    genf(0);

    for (int kc = 0; kc < 32; kc++) {
        int s = kc & 1, ns = s ^ 1;
        bool have = (kc < 31);
        if (have) ldgc(kc + 1);
        __syncthreads();
        if (have) storec(ns);
        mmastep(s, 0);
        mmastep(s, 1);
        if (have) {
            __syncthreads();
            genf(ns);
        }
        mmastep(s, 2);
        mmastep(s, 3);
    }

    // ---- epilogue: bias + relu; scatter real pairs to g_h, pseudo pairs to g_row ----
    int qrow = lane >> 2, qcol = (lane & 3) * 2;
#pragma unroll
    for (int am = 0; am < 4; am++) {
        int mb = wm * 64 + am * 16;
        float bias0 = b1[m0 + mb + qrow];
        float bias1 = b1[m0 + mb + qrow + 8];
#pragma unroll
        for (int bn = 0; bn < 8; bn++) {
            int n = wn * 64 + bn * 8 + qcol;
#pragma unroll
            for (int r = 0; r < 4; r++) {
                int mrow = mb + qrow + (r >> 1) * 8;
                int nn = n + (r & 1);
                float v = acc[am][bn][r] + ((r >> 1) ? bias1 : bias0);
                v = fmaxf(v, 0.f);
                int sa = nn >> 4, sj = nn & 15;
                int ri = six[sa], rj = six[16 + sj];
                int o = m0 + mrow;
                if (ri >= 0 && rj >= 0) {
                    float* hp = g_h + ((size_t)o << 16);
                    hp[ri * 256 + rj] = v;
                    hp[rj * 256 + ri] = v;
                } else {
                    int pa = i0 + sa, pb = j0 + sj;
                    if (pa == U && rj >= 0)      g_row[(size_t)o * 257 + rj] = v;
                    else if (pb == U && ri >= 0) g_row[(size_t)o * 257 + ri] = v;
                    else if (pa == U && pb == U) g_row[(size_t)o * 257 + 256] = v;
                }
            }
        }
    }
}

// ---------------- 7x7 conv: halo loads select g_h (real pairs) or g_row (masked) ----------------
__global__ __launch_bounds__(256) void k_conv2(const float* __restrict__ w2) {
    int jb = blockIdx.x, ib = blockIdx.y;
    if (jb < ib) return;
    int g = blockIdx.z;
    __shared__ float sT[38][40];
    __shared__ float sKc[49];
    __shared__ int sMi[38], sMj[38];   // 0 = real, 1 = masked, 2 = out-of-bounds
    int tid = threadIdx.x;
    int tx = tid & 31, ty = tid >> 5;
    int i0 = ib * 32, j0 = jb * 32;
    int rbase = ty * 4;
    float acc[4] = {0.f, 0.f, 0.f, 0.f};

    if (tid < 38) {
        int gi = i0 - 3 + tid;
        sMi[tid] = ((unsigned)gi < 256u) ? ((g_mask[gi] == 0.f) ? 1 : 0) : 2;
        int gj = j0 - 3 + tid;
        sMj[tid] = ((unsigned)gj < 256u) ? ((g_mask[gj] == 0.f) ? 1 : 0) : 2;
    }
    __syncthreads();

    for (int c = g * 64; c < g * 64 + 64; c++) {
        __syncthreads();
        const float* hp = g_h + ((size_t)c << 16);
        const float* rw = g_row + (size_t)c * 257;
        for (int t = tid; t < 38 * 38; t += 256) {
            int r = t / 38, cc = t - r * 38;
            int mi = sMi[r], mj = sMj[cc];
            float v = 0.f;
            if ((mi | mj) < 2) {                        // both in-bounds
                int gi = i0 - 3 + r, gj = j0 - 3 + cc;
                const float* p;
                if ((mi | mj) == 0)      p = hp + gi * 256 + gj;  // real pair
                else if ((mi & mj) == 1) p = rw + 256;            // both masked
                else if (mi)             p = rw + gj;             // i masked
                else                     p = rw + gi;             // j masked
                v = *p;
            }
            sT[r][cc] = v;
        }
        if (tid < 49) sKc[tid] = w2[c * 49 + tid];
        __syncthreads();
        float wk[49];
#pragma unroll
        for (int q = 0; q < 49; q++) wk[q] = sKc[q];
#pragma unroll
        for (int rr = 0; rr < 10; rr++) {
            float seg[7];
#pragma unroll
            for (int b = 0; b < 7; b++) seg[b] = sT[rbase + rr][tx + b];
#pragma unroll
            for (int r = 0; r < 4; r++) {
                int a = rr - r;
                if (a >= 0 && a < 7) {
#pragma unroll
                    for (int b = 0; b < 7; b++)
                        acc[r] += wk[a * 7 + b] * seg[b];
                }
            }
        }
    }
#pragma unroll
    for (int r = 0; r < 4; r++) {
        int i = i0 + rbase + r, j = j0 + tx;
        g_part[g * NPAIR + i * 256 + j] = acc[r];
    }
}

__global__ void k_red(const float* __restrict__ b2, float* __restrict__ out) {
    int idx = blockIdx.x * 256 + threadIdx.x;
    int i = idx >> 8, j = idx & 255;
    if (j < i) return;
    float s = b2[0];
#pragma unroll
    for (int g = 0; g < 16; g++) s += g_part[g * NPAIR + idx];
    float v = 1.f / (1.f + expf(-s));
    out[NEC + i * 256 + j] = v;
    out[NEC + j * 256 + i] = v;
}

extern "C" void kernel_launch(void* const* d_in, const int* in_sizes, int n_in,
                              void* d_out, int out_size) {
    const float* attn    = (const float*)d_in[0];
    const float* pooled  = (const float*)d_in[1];
    const int*   am      = (const int*)d_in[2];
    const float* lin1_w  = (const float*)d_in[3];
    const float* lin1_b  = (const float*)d_in[4];
    const float* cls_w   = (const float*)d_in[5];
    const float* cls_b   = (const float*)d_in[6];
    const float* conv1_w = (const float*)d_in[7];
    const float* conv1_b = (const float*)d_in[8];
    const float* conv2_w = (const float*)d_in[9];
    const float* conv2_b = (const float*)d_in[10];
    float* out = (float*)d_out;

    cudaFuncSetAttribute(k_hmma, cudaFuncAttributeMaxDynamicSharedMemorySize, SMEM_BYTES);

    // order: heavy kernels early (ncu -s 5 -c 1 lands on k_hmma/k_conv2 region)
    k_mask<<<1, 256>>>(am);
    k_z<<<256, 256>>>(attn);
    k_wsplit<<<8192, 256>>>(conv1_w);
    k_hmma<<<dim3(8, 17, 17), 256, SMEM_BYTES>>>(conv1_b);
    k_conv2<<<dim3(8, 8, 16), 256>>>(conv2_w);
    k_red<<<256, 256>>>(conv2_b, out);
    k_lin1<<<128, 256>>>(pooled, lin1_w, lin1_b);
    k_cls<<<250, 256>>>(cls_w, cls_b, out);
}

// round 13
// speedup vs baseline: 6.1386x; 1.1337x over previous
#include <cuda_runtime.h>
#include <cuda_bf16.h>
#include <cstdint>
#include <math.h>

#define L 256
#define C 1024
#define NEC 2000
#define NPAIR 65536

// ---------------- scratch (__device__ globals; no allocations) ----------------
__device__ float g_mask[L];
__device__ int   g_idx[257];                       // compacted unmasked indices
__device__ int   g_U;                              // count of unmasked positions
__device__ float g_z[C * L];                       // z[c][l], masked, transposed
__device__ float g_tmp[C];                         // lin1 output
__device__ float g_h[(size_t)C * NPAIR];           // h[o][i][j]  (sparse: real pairs only)
__device__ float g_row[(size_t)C * 257];           // pseudo-pair values: [o][real j], [o][256]=const
__device__ float g_part[16 * NPAIR];               // conv2 channel-group partials
__device__ __nv_bfloat16 g_whi[(size_t)C * 2048];  // W split hi, chunk-interleaved
__device__ __nv_bfloat16 g_wlo[(size_t)C * 2048];  // W split lo

// ---------------- helpers ----------------
__device__ __forceinline__ uint32_t smem_to_u32(const void* p) {
    uint32_t a;
    asm("{ .reg .u64 t; cvta.to.shared.u64 t, %1; cvt.u32.u64 %0, t; }" : "=r"(a) : "l"(p));
    return a;
}
#define CVT_BF16X2(res, a, b) \
    asm("cvt.rn.satfinite.bf16x2.f32 %0, %1, %2;" : "=r"(res) : "f"(b), "f"(a))
#define SWZ128(x) ((x) ^ (((x) >> 3) & 0x70))

__device__ __forceinline__ void ldsm_x4(uint32_t addr, uint32_t* r) {
    asm volatile("ldmatrix.sync.aligned.m8n8.x4.shared.b16 {%0,%1,%2,%3}, [%4];"
                 : "=r"(r[0]), "=r"(r[1]), "=r"(r[2]), "=r"(r[3]) : "r"(addr));
}
__device__ __forceinline__ void mma16816(float* c, const uint32_t* a, uint32_t b0, uint32_t b1) {
    asm volatile(
        "mma.sync.aligned.m16n8k16.row.col.f32.bf16.bf16.f32 "
        "{%0,%1,%2,%3}, {%4,%5,%6,%7}, {%8,%9}, {%0,%1,%2,%3};"
        : "+f"(c[0]), "+f"(c[1]), "+f"(c[2]), "+f"(c[3])
        : "r"(a[0]), "r"(a[1]), "r"(a[2]), "r"(a[3]), "r"(b0), "r"(b1));
}

// SMEM layout (byte offsets from 1024-aligned base), double-buffered
#define SB_(s) ((s) * 98304)
#define SM_AH(s) (SB_(s))
#define SM_AL(s) (SB_(s) + 16384)
#define SM_BH(s) (SB_(s) + 32768)
#define SM_BL(s) (SB_(s) + 65536)
#define SM_ZC(s) (196608 + (s) * 4352)
#define SM_SIX 205312
#define SMEM_BYTES (205312 + 128 + 1024)

// ---------------- prep: mask + compacted index list ----------------
__global__ void k_mask(const int* __restrict__ am) {
    __shared__ int red[256];
    __shared__ int scn[256];
    int l = threadIdx.x;
    int v = am[l];
    red[l] = v;
    __syncthreads();
    for (int off = 128; off; off >>= 1) {
        if (l < off) red[l] += red[l + off];
        __syncthreads();
    }
    int s = red[0];
    float m = (float)v;
    if (l == 0 || l == s) m = 0.f;
    g_mask[l] = m;
    int flag = (m != 0.f) ? 1 : 0;
    scn[l] = flag;
    __syncthreads();
    for (int off = 1; off < 256; off <<= 1) {
        int t = (l >= off) ? scn[l - off] : 0;
        __syncthreads();
        scn[l] += t;
        __syncthreads();
    }
    if (flag) g_idx[scn[l] - 1] = l;
    if (l == 255) g_U = scn[255];
}

__global__ void k_z(const float* __restrict__ attn) {
    int l = blockIdx.x;
    float m = g_mask[l];
    for (int c = threadIdx.x; c < C; c += blockDim.x)
        g_z[c * L + l] = attn[l * C + c] * m;
}

// ---------------- W hi/lo split, chunk-interleaved, float4 vectorized ----------------
__global__ void k_wsplit(const float* __restrict__ W) {
    int idx = (blockIdx.x * 256 + threadIdx.x) * 4;   // 4 elems/thread; runs never cross the 32-boundary
    int o = idx >> 11;
    int k = idx & 2047;
    int kc = k >> 6, kk = k & 63;
    int c = (kk < 32) ? (kc * 32 + kk) : (1024 + kc * 32 + kk - 32);
    float4 v = *(const float4*)(W + (size_t)o * 2048 + c);
    __nv_bfloat16 h0 = __float2bfloat16_rn(v.x), h1 = __float2bfloat16_rn(v.y);
    __nv_bfloat16 h2 = __float2bfloat16_rn(v.z), h3 = __float2bfloat16_rn(v.w);
    __nv_bfloat16 l0 = __float2bfloat16_rn(v.x - __bfloat162float(h0));
    __nv_bfloat16 l1 = __float2bfloat16_rn(v.y - __bfloat162float(h1));
    __nv_bfloat16 l2 = __float2bfloat16_rn(v.z - __bfloat162float(h2));
    __nv_bfloat16 l3 = __float2bfloat16_rn(v.w - __bfloat162float(h3));
    __nv_bfloat162* dh = (__nv_bfloat162*)(g_whi + idx);
    __nv_bfloat162* dl = (__nv_bfloat162*)(g_wlo + idx);
    dh[0] = __halves2bfloat162(h0, h1);
    dh[1] = __halves2bfloat162(h2, h3);
    dl[0] = __halves2bfloat162(l0, l1);
    dl[1] = __halves2bfloat162(l2, l3);
}

// ---------------- logits head ----------------
__global__ void k_lin1(const float* __restrict__ pooled, const float* __restrict__ w,
                       const float* __restrict__ b) {
    int gw = (blockIdx.x * blockDim.x + threadIdx.x) >> 5;
    int lane = threadIdx.x & 31;
    if (gw >= C) return;
    const float* row = w + (size_t)gw * C;
    float s = 0.f;
    for (int c2 = lane; c2 < C; c2 += 32) s += row[c2] * pooled[c2];
#pragma unroll
    for (int off = 16; off; off >>= 1) s += __shfl_xor_sync(0xffffffffu, s, off);
    if (lane == 0) g_tmp[gw] = s + b[gw];
}

__global__ void k_cls(const float* __restrict__ w, const float* __restrict__ b,
                      float* __restrict__ out) {
    int gw = (blockIdx.x * blockDim.x + threadIdx.x) >> 5;
    int lane = threadIdx.x & 31;
    if (gw >= NEC) return;
    const float* row = w + (size_t)gw * C;
    float s = 0.f;
    for (int c2 = lane; c2 < C; c2 += 32) s += row[c2] * g_tmp[c2];
#pragma unroll
    for (int off = 16; off; off >>= 1) s += __shfl_xor_sync(0xffffffffu, s, off);
    if (lane == 0) out[gw] = s + b[gw];
}

// ---------------- main GEMM: compacted pairs (unmasked + 1 pseudo), 3xBF16 split ----------------
__global__ void __launch_bounds__(256, 1) k_hmma(const float* __restrict__ b1) {
    int ib = blockIdx.y, jb = blockIdx.z;
    int U = g_U;
    int T = (U + 16) >> 4;
    if (jb < ib || ib >= T || jb >= T) return;
    int m0 = blockIdx.x * 128;
    int i0 = ib * 16, j0 = jb * 16;

    extern __shared__ char smem_raw[];
    char* sm = (char*)(((uintptr_t)smem_raw + 1023) & ~(uintptr_t)1023);
    uint32_t sb = smem_to_u32(sm);
    int* six = (int*)(sm + SM_SIX);

    int tid = threadIdx.x, wid = tid >> 5, lane = tid & 31;
    int wm = wid >> 2, wn = wid & 3;
    int arow = lane & 15, aseg = lane >> 4;
    int brow = (lane & 7) + ((lane >> 4) << 3);
    int bhalf = (lane >> 3) & 1;

    if (tid < 32) {
        int a = (tid < 16) ? (i0 + tid) : (j0 + tid - 16);
        six[tid] = (a < U) ? g_idx[a] : -1;
    }
    __syncthreads();

    float acc[4][8][4];
#pragma unroll
    for (int a = 0; a < 4; a++)
#pragma unroll
        for (int b = 0; b < 8; b++)
#pragma unroll
            for (int r = 0; r < 4; r++) acc[a][b][r] = 0.f;

    float pz[4];
    float4 pwh[4], pwl[4];

    auto ldgc = [&](int kc) {
        int c0 = kc * 32;
#pragma unroll
        for (int r = 0; r < 4; r++) {
            int id2 = tid + r * 256;
            int ch = id2 >> 5, l2 = id2 & 31;
            int pos = six[l2];
            pz[r] = (pos >= 0) ? g_z[(c0 + ch) * L + pos] : 0.f;
        }
#pragma unroll
        for (int r = 0; r < 4; r++) {
            int q = tid + r * 256;
            int row = q >> 3, seg = q & 7;
            pwh[r] = *(const float4*)((const char*)(g_whi + (size_t)(m0 + row) * 2048 + kc * 64) + seg * 16);
            pwl[r] = *(const float4*)((const char*)(g_wlo + (size_t)(m0 + row) * 2048 + kc * 64) + seg * 16);
        }
    };
    auto storec = [&](int st) {
        float* zcs = (float*)(sm + SM_ZC(st));
#pragma unroll
        for (int r = 0; r < 4; r++) {
            int id2 = tid + r * 256;
            int ch = id2 >> 5, l2 = id2 & 31;
            zcs[ch * 33 + l2] = pz[r];
        }
#pragma unroll
        for (int r = 0; r < 4; r++) {
            int q = tid + r * 256;
            int row = q >> 3, seg = q & 7;
            uint32_t swo = SWZ128((uint32_t)(row * 128 + seg * 16));
            *(float4*)(sm + SM_AH(st) + swo) = pwh[r];
            *(float4*)(sm + SM_AL(st) + swo) = pwl[r];
        }
    };
    int ii = tid >> 4, jj = tid & 15;
    auto genf = [&](int st) {
        const float* zi = (const float*)(sm + SM_ZC(st)) + ii;
        const float* zj = (const float*)(sm + SM_ZC(st)) + 16 + jj;
#pragma unroll
        for (int g = 0; g < 4; g++) {
            uint32_t dh[4], dl[4], mh[4], ml[4];
#pragma unroll
            for (int u = 0; u < 4; u++) {
                int ch = g * 8 + u * 2;
                float a0 = zi[ch * 33], a1 = zi[(ch + 1) * 33];
                float b0 = zj[ch * 33], b1v = zj[(ch + 1) * 33];
                float d0 = fabsf(a0 - b0), d1 = fabsf(a1 - b1v);
                float p0 = a0 * b0, p1 = a1 * b1v;
                uint32_t rh; CVT_BF16X2(rh, d0, d1);
                float h0 = __uint_as_float(rh << 16);
                float h1 = __uint_as_float(rh & 0xffff0000u);
                uint32_t rl; CVT_BF16X2(rl, d0 - h0, d1 - h1);
                uint32_t qh; CVT_BF16X2(qh, p0, p1);
                float q0 = __uint_as_float(qh << 16);
                float q1 = __uint_as_float(qh & 0xffff0000u);
                uint32_t ql; CVT_BF16X2(ql, p0 - q0, p1 - q1);
                dh[u] = rh; dl[u] = rl; mh[u] = qh; ml[u] = ql;
            }
            uint32_t bod = SWZ128((uint32_t)(tid * 128 + g * 16));
            uint32_t bom = SWZ128((uint32_t)(tid * 128 + 64 + g * 16));
            *(uint4*)(sm + SM_BH(st) + bod) = make_uint4(dh[0], dh[1], dh[2], dh[3]);
            *(uint4*)(sm + SM_BL(st) + bod) = make_uint4(dl[0], dl[1], dl[2], dl[3]);
            *(uint4*)(sm + SM_BH(st) + bom) = make_uint4(mh[0], mh[1], mh[2], mh[3]);
            *(uint4*)(sm + SM_BL(st) + bom) = make_uint4(ml[0], ml[1], ml[2], ml[3]);
        }
    };
    auto mmastep = [&](int st, int ks) {
        int kb = ks * 32;
        uint32_t af[4][4], bh[4][4], bl[4][4];
#pragma unroll
        for (int am = 0; am < 4; am++) {
            uint32_t off = SWZ128((uint32_t)((wm * 64 + am * 16 + arow) * 128 + kb + aseg * 16));
            ldsm_x4(sb + SM_AH(st) + off, af[am]);
        }
#pragma unroll
        for (int bq = 0; bq < 4; bq++) {
            uint32_t off = SWZ128((uint32_t)((wn * 64 + bq * 16 + brow) * 128 + kb + bhalf * 16));
            ldsm_x4(sb + SM_BH(st) + off, bh[bq]);
            ldsm_x4(sb + SM_BL(st) + off, bl[bq]);
        }
#pragma unroll
        for (int am = 0; am < 4; am++)
#pragma unroll
            for (int bq = 0; bq < 4; bq++) {
                mma16816(acc[am][2 * bq], af[am], bh[bq][0], bh[bq][1]);
                mma16816(acc[am][2 * bq + 1], af[am], bh[bq][2], bh[bq][3]);
            }
#pragma unroll
        for (int am = 0; am < 4; am++)
#pragma unroll
            for (int bq = 0; bq < 4; bq++) {
                mma16816(acc[am][2 * bq], af[am], bl[bq][0], bl[bq][1]);
                mma16816(acc[am][2 * bq + 1], af[am], bl[bq][2], bl[bq][3]);
            }
#pragma unroll
        for (int am = 0; am < 4; am++) {
            uint32_t off = SWZ128((uint32_t)((wm * 64 + am * 16 + arow) * 128 + kb + aseg * 16));
            ldsm_x4(sb + SM_AL(st) + off, af[am]);
        }
#pragma unroll
        for (int am = 0; am < 4; am++)
#pragma unroll
            for (int bq = 0; bq < 4; bq++) {
                mma16816(acc[am][2 * bq], af[am], bh[bq][0], bh[bq][1]);
                mma16816(acc[am][2 * bq + 1], af[am], bh[bq][2], bh[bq][3]);
            }
    };

    ldgc(0);
    storec(0);
    __syncthreads();
    genf(0);

    for (int kc = 0; kc < 32; kc++) {
        int s = kc & 1, ns = s ^ 1;
        bool have = (kc < 31);
        if (have) ldgc(kc + 1);
        __syncthreads();
        if (have) storec(ns);
        mmastep(s, 0);
        mmastep(s, 1);
        if (have) {
            __syncthreads();
            genf(ns);
        }
        mmastep(s, 2);
        mmastep(s, 3);
    }

    int qrow = lane >> 2, qcol = (lane & 3) * 2;
#pragma unroll
    for (int am = 0; am < 4; am++) {
        int mb = wm * 64 + am * 16;
        float bias0 = b1[m0 + mb + qrow];
        float bias1 = b1[m0 + mb + qrow + 8];
#pragma unroll
        for (int bn = 0; bn < 8; bn++) {
            int n = wn * 64 + bn * 8 + qcol;
#pragma unroll
            for (int r = 0; r < 4; r++) {
                int mrow = mb + qrow + (r >> 1) * 8;
                int nn = n + (r & 1);
                float v = acc[am][bn][r] + ((r >> 1) ? bias1 : bias0);
                v = fmaxf(v, 0.f);
                int sa = nn >> 4, sj = nn & 15;
                int ri = six[sa], rj = six[16 + sj];
                int o = m0 + mrow;
                if (ri >= 0 && rj >= 0) {
                    float* hp = g_h + ((size_t)o << 16);
                    hp[ri * 256 + rj] = v;
                    hp[rj * 256 + ri] = v;
                } else {
                    int pa = i0 + sa, pb = j0 + sj;
                    if (pa == U && rj >= 0)      g_row[(size_t)o * 257 + rj] = v;
                    else if (pb == U && ri >= 0) g_row[(size_t)o * 257 + ri] = v;
                    else if (pa == U && pb == U) g_row[(size_t)o * 257 + 256] = v;
                }
            }
        }
    }
}

// ---------------- 7x7 conv: masked-row factorization + double-buffered prefetch ----------------
// Real rows: standard 7-tap FMA from sT. Masked rows: single add of precomputed S[a][j]
// where S[a][j] = sum_b K(a,b) * u(j+b), u = column-classified g_row value.
__global__ __launch_bounds__(256) void k_conv2(const float* __restrict__ w2) {
    int jb = blockIdx.x, ib = blockIdx.y;
    if (jb < ib) return;
    int g = blockIdx.z;
    __shared__ float sT[2][38][40];
    __shared__ float su[2][40];
    __shared__ float sKc[2][49];
    __shared__ float sS[2][7][32];
    __shared__ int sMi[38], sMj[38];   // 0 = real, 1 = masked, 2 = out-of-bounds
    int tid = threadIdx.x;
    int tx = tid & 31, ty = tid >> 5;
    int i0 = ib * 32, j0 = jb * 32;
    int rbase = ty * 4;
    float acc[4] = {0.f, 0.f, 0.f, 0.f};

    if (tid < 38) {
        int gi = i0 - 3 + tid;
        sMi[tid] = ((unsigned)gi < 256u) ? ((g_mask[gi] == 0.f) ? 1 : 0) : 2;
        int gj = j0 - 3 + tid;
        sMj[tid] = ((unsigned)gj < 256u) ? ((g_mask[gj] == 0.f) ? 1 : 0) : 2;
    }
    __syncthreads();

    float rT[6], rU, rK;
    auto ldg_stage = [&](int c) {
        const float* hp = g_h + ((size_t)c << 16);
        const float* rw = g_row + (size_t)c * 257;
#pragma unroll
        for (int q = 0; q < 6; q++) {
            rT[q] = 0.f;
            int t = tid + q * 256;
            if (t < 38 * 38) {
                int r = t / 38, cc = t - r * 38;
                if (sMi[r] == 0) {                 // only real rows are consumed from sT
                    int gi = i0 - 3 + r, gj = j0 - 3 + cc;
                    int mj = sMj[cc];
                    if (mj == 0)      rT[q] = hp[gi * 256 + gj];
                    else if (mj == 1) rT[q] = rw[gi];
                }
            }
        }
        rU = 0.f;
        if (tid < 38) {
            int mj = sMj[tid];
            if (mj == 0)      rU = rw[j0 - 3 + tid];
            else if (mj == 1) rU = rw[256];
        }
        rK = (tid < 49) ? w2[c * 49 + tid] : 0.f;
    };
    auto sts_stage = [&](int s) {
#pragma unroll
        for (int q = 0; q < 6; q++) {
            int t = tid + q * 256;
            if (t < 38 * 38) {
                int r = t / 38, cc = t - r * 38;
                sT[s][r][cc] = rT[q];
            }
        }
        if (tid < 38) su[s][tid] = rU;
        if (tid < 49) sKc[s][tid] = rK;
    };
    auto computeS = [&](int s) {
        if (tid < 224) {
            int a = tid >> 5, j = tid & 31;
            float v = 0.f;
#pragma unroll
            for (int b = 0; b < 7; b++) v += sKc[s][a * 7 + b] * su[s][j + b];
            sS[s][a][j] = v;
        }
    };

    // prologue
    ldg_stage(g * 64);
    sts_stage(0);
    __syncthreads();
    computeS(0);

    for (int ci = 0; ci < 64; ci++) {
        int c = g * 64 + ci;
        int s = ci & 1, ns = s ^ 1;
        bool have = (ci < 63);
        if (have) ldg_stage(c + 1);     // LDG latency overlaps barrier + compute
        __syncthreads();                 // (A) sS[s] visible; sT[ns] free (readers done)
        if (have) sts_stage(ns);

        float wk[49];
#pragma unroll
        for (int q = 0; q < 49; q++) wk[q] = sKc[s][q];
#pragma unroll
        for (int rr = 0; rr < 10; rr++) {
            int cls = sMi[rbase + rr];
            if (cls == 0) {
                float seg[7];
#pragma unroll
                for (int b = 0; b < 7; b++) seg[b] = sT[s][rbase + rr][tx + b];
#pragma unroll
                for (int r = 0; r < 4; r++) {
                    int a = rr - r;
                    if (a >= 0 && a < 7) {
#pragma unroll
                        for (int b = 0; b < 7; b++)
                            acc[r] += wk[a * 7 + b] * seg[b];
                    }
                }
            } else if (cls == 1) {
#pragma unroll
                for (int r = 0; r < 4; r++) {
                    int a = rr - r;
                    if (a >= 0 && a < 7) acc[r] += sS[s][a][tx];
                }
            }
        }

        if (have) {
            __syncthreads();             // (B) sts(ns) complete
            computeS(ns);                // sS[ns] for next iteration (visible after next (A))
        }
    }

#pragma unroll
    for (int r = 0; r < 4; r++) {
        int i = i0 + rbase + r, j = j0 + tx;
        g_part[g * NPAIR + i * 256 + j] = acc[r];
    }
}

__global__ void k_red(const float* __restrict__ b2, float* __restrict__ out) {
    int idx = blockIdx.x * 256 + threadIdx.x;
    int i = idx >> 8, j = idx & 255;
    if (j < i) return;
    float s = b2[0];
#pragma unroll
    for (int g = 0; g < 16; g++) s += g_part[g * NPAIR + idx];
    float v = 1.f / (1.f + expf(-s));
    out[NEC + i * 256 + j] = v;
    out[NEC + j * 256 + i] = v;
}

extern "C" void kernel_launch(void* const* d_in, const int* in_sizes, int n_in,
                              void* d_out, int out_size) {
    const float* attn    = (const float*)d_in[0];
    const float* pooled  = (const float*)d_in[1];
    const int*   am      = (const int*)d_in[2];
    const float* lin1_w  = (const float*)d_in[3];
    const float* lin1_b  = (const float*)d_in[4];
    const float* cls_w   = (const float*)d_in[5];
    const float* cls_b   = (const float*)d_in[6];
    const float* conv1_w = (const float*)d_in[7];
    const float* conv1_b = (const float*)d_in[8];
    const float* conv2_w = (const float*)d_in[9];
    const float* conv2_b = (const float*)d_in[10];
    float* out = (float*)d_out;

    cudaFuncSetAttribute(k_hmma, cudaFuncAttributeMaxDynamicSharedMemorySize, SMEM_BYTES);

    k_mask<<<1, 256>>>(am);
    k_z<<<256, 256>>>(attn);
    k_wsplit<<<2048, 256>>>(conv1_w);
    k_hmma<<<dim3(8, 17, 17), 256, SMEM_BYTES>>>(conv1_b);
    k_conv2<<<dim3(8, 8, 16), 256>>>(conv2_w);
    k_red<<<256, 256>>>(conv2_b, out);
    k_lin1<<<128, 256>>>(pooled, lin1_w, lin1_b);
    k_cls<<<250, 256>>>(cls_w, cls_b, out);
}

// round 14
// speedup vs baseline: 8.1921x; 1.3345x over previous
#include <cuda_runtime.h>
#include <cuda_fp16.h>
#include <cstdint>
#include <math.h>

#define L 256
#define C 1024
#define NEC 2000
#define NPAIR 65536

// ---------------- scratch (__device__ globals; no allocations) ----------------
__device__ float g_mask[L];
__device__ int   g_idx[257];                       // compacted unmasked indices
__device__ int   g_U;                              // count of unmasked positions
__device__ float g_z[C * L];                       // z[c][l], masked, transposed
__device__ float g_tmp[C];                         // lin1 output
__device__ float g_h[(size_t)C * NPAIR];           // h[o][i][j]  (sparse: real pairs only)
__device__ float g_row[(size_t)C * 257];           // pseudo-pair values: [o][real j], [o][256]=const
__device__ float g_part[16 * NPAIR];               // conv2 channel-group partials
__device__ __half g_wh[(size_t)C * 2048];          // W in fp16, chunk-interleaved

// ---------------- helpers ----------------
__device__ __forceinline__ uint32_t smem_to_u32(const void* p) {
    uint32_t a;
    asm("{ .reg .u64 t; cvta.to.shared.u64 t, %1; cvt.u32.u64 %0, t; }" : "=r"(a) : "l"(p));
    return a;
}
#define CVT_F16X2(res, a, b) \
    asm("cvt.rn.f16x2.f32 %0, %1, %2;" : "=r"(res) : "f"(b), "f"(a))
#define SWZ128(x) ((x) ^ (((x) >> 3) & 0x70))

__device__ __forceinline__ void ldsm_x4(uint32_t addr, uint32_t* r) {
    asm volatile("ldmatrix.sync.aligned.m8n8.x4.shared.b16 {%0,%1,%2,%3}, [%4];"
                 : "=r"(r[0]), "=r"(r[1]), "=r"(r[2]), "=r"(r[3]) : "r"(addr));
}
__device__ __forceinline__ void mma16816(float* c, const uint32_t* a, uint32_t b0, uint32_t b1) {
    asm volatile(
        "mma.sync.aligned.m16n8k16.row.col.f32.f16.f16.f32 "
        "{%0,%1,%2,%3}, {%4,%5,%6,%7}, {%8,%9}, {%0,%1,%2,%3};"
        : "+f"(c[0]), "+f"(c[1]), "+f"(c[2]), "+f"(c[3])
        : "r"(a[0]), "r"(a[1]), "r"(a[2]), "r"(a[3]), "r"(b0), "r"(b1));
}

// SMEM layout (byte offsets from 1024-aligned base), double-buffered
#define SM_A(s)  ((s) * 49152)
#define SM_B(s)  ((s) * 49152 + 16384)
#define SM_ZC(s) (98304 + (s) * 4352)
#define SM_SIX 107008
#define SMEM_BYTES (107008 + 128 + 1024)

// ---------------- prep: mask + compacted index list ----------------
__global__ void k_mask(const int* __restrict__ am) {
    __shared__ int red[256];
    __shared__ int scn[256];
    int l = threadIdx.x;
    int v = am[l];
    red[l] = v;
    __syncthreads();
    for (int off = 128; off; off >>= 1) {
        if (l < off) red[l] += red[l + off];
        __syncthreads();
    }
    int s = red[0];
    float m = (float)v;
    if (l == 0 || l == s) m = 0.f;
    g_mask[l] = m;
    int flag = (m != 0.f) ? 1 : 0;
    scn[l] = flag;
    __syncthreads();
    for (int off = 1; off < 256; off <<= 1) {
        int t = (l >= off) ? scn[l - off] : 0;
        __syncthreads();
        scn[l] += t;
        __syncthreads();
    }
    if (flag) g_idx[scn[l] - 1] = l;
    if (l == 255) g_U = scn[255];
}

__global__ void k_z(const float* __restrict__ attn) {
    int l = blockIdx.x;
    float m = g_mask[l];
    for (int c = threadIdx.x; c < C; c += blockDim.x)
        g_z[c * L + l] = attn[l * C + c] * m;
}

// ---------------- W -> fp16, chunk-interleaved, float4 vectorized ----------------
__global__ void k_wsplit(const float* __restrict__ W) {
    int idx = (blockIdx.x * 256 + threadIdx.x) * 4;
    int o = idx >> 11;
    int k = idx & 2047;
    int kc = k >> 6, kk = k & 63;
    int c = (kk < 32) ? (kc * 32 + kk) : (1024 + kc * 32 + kk - 32);
    float4 v = *(const float4*)(W + (size_t)o * 2048 + c);
    __half2* dh = (__half2*)(g_wh + idx);
    dh[0] = __floats2half2_rn(v.x, v.y);
    dh[1] = __floats2half2_rn(v.z, v.w);
}

// ---------------- logits head ----------------
__global__ void k_lin1(const float* __restrict__ pooled, const float* __restrict__ w,
                       const float* __restrict__ b) {
    int gw = (blockIdx.x * blockDim.x + threadIdx.x) >> 5;
    int lane = threadIdx.x & 31;
    if (gw >= C) return;
    const float* row = w + (size_t)gw * C;
    float s = 0.f;
    for (int c2 = lane; c2 < C; c2 += 32) s += row[c2] * pooled[c2];
#pragma unroll
    for (int off = 16; off; off >>= 1) s += __shfl_xor_sync(0xffffffffu, s, off);
    if (lane == 0) g_tmp[gw] = s + b[gw];
}

__global__ void k_cls(const float* __restrict__ w, const float* __restrict__ b,
                      float* __restrict__ out) {
    int gw = (blockIdx.x * blockDim.x + threadIdx.x) >> 5;
    int lane = threadIdx.x & 31;
    if (gw >= NEC) return;
    const float* row = w + (size_t)gw * C;
    float s = 0.f;
    for (int c2 = lane; c2 < C; c2 += 32) s += row[c2] * g_tmp[c2];
#pragma unroll
    for (int off = 16; off; off >>= 1) s += __shfl_xor_sync(0xffffffffu, s, off);
    if (lane == 0) out[gw] = s + b[gw];
}

// ---------------- main GEMM: compacted pairs, single-pass FP16 ----------------
__global__ void __launch_bounds__(256, 1) k_hmma(const float* __restrict__ b1) {
    int ib = blockIdx.y, jb = blockIdx.z;
    int U = g_U;
    int T = (U + 16) >> 4;
    if (jb < ib || ib >= T || jb >= T) return;
    int m0 = blockIdx.x * 128;
    int i0 = ib * 16, j0 = jb * 16;

    extern __shared__ char smem_raw[];
    char* sm = (char*)(((uintptr_t)smem_raw + 1023) & ~(uintptr_t)1023);
    uint32_t sb = smem_to_u32(sm);
    int* six = (int*)(sm + SM_SIX);

    int tid = threadIdx.x, wid = tid >> 5, lane = tid & 31;
    int wm = wid >> 2, wn = wid & 3;
    int arow = lane & 15, aseg = lane >> 4;
    int brow = (lane & 7) + ((lane >> 4) << 3);
    int bhalf = (lane >> 3) & 1;

    if (tid < 32) {
        int a = (tid < 16) ? (i0 + tid) : (j0 + tid - 16);
        six[tid] = (a < U) ? g_idx[a] : -1;
    }
    __syncthreads();

    float acc[4][8][4];
#pragma unroll
    for (int a = 0; a < 4; a++)
#pragma unroll
        for (int b = 0; b < 8; b++)
#pragma unroll
            for (int r = 0; r < 4; r++) acc[a][b][r] = 0.f;

    float pz[4];
    float4 pw[4];

    auto ldgc = [&](int kc) {
        int c0 = kc * 32;
#pragma unroll
        for (int r = 0; r < 4; r++) {
            int id2 = tid + r * 256;
            int ch = id2 >> 5, l2 = id2 & 31;
            int pos = six[l2];
            pz[r] = (pos >= 0) ? g_z[(c0 + ch) * L + pos] : 0.f;
        }
#pragma unroll
        for (int r = 0; r < 4; r++) {
            int q = tid + r * 256;
            int row = q >> 3, seg = q & 7;
            pw[r] = *(const float4*)((const char*)(g_wh + (size_t)(m0 + row) * 2048 + kc * 64) + seg * 16);
        }
    };
    auto storec = [&](int st) {
        float* zcs = (float*)(sm + SM_ZC(st));
#pragma unroll
        for (int r = 0; r < 4; r++) {
            int id2 = tid + r * 256;
            int ch = id2 >> 5, l2 = id2 & 31;
            zcs[ch * 33 + l2] = pz[r];
        }
#pragma unroll
        for (int r = 0; r < 4; r++) {
            int q = tid + r * 256;
            int row = q >> 3, seg = q & 7;
            uint32_t swo = SWZ128((uint32_t)(row * 128 + seg * 16));
            *(float4*)(sm + SM_A(st) + swo) = pw[r];
        }
    };
    int ii = tid >> 4, jj = tid & 15;
    auto genf = [&](int st) {
        const float* zi = (const float*)(sm + SM_ZC(st)) + ii;
        const float* zj = (const float*)(sm + SM_ZC(st)) + 16 + jj;
#pragma unroll
        for (int g = 0; g < 4; g++) {
            uint32_t dh[4], mh[4];
#pragma unroll
            for (int u = 0; u < 4; u++) {
                int ch = g * 8 + u * 2;
                float a0 = zi[ch * 33], a1 = zi[(ch + 1) * 33];
                float b0 = zj[ch * 33], b1v = zj[(ch + 1) * 33];
                float d0 = fabsf(a0 - b0), d1 = fabsf(a1 - b1v);
                float p0 = a0 * b0, p1 = a1 * b1v;
                uint32_t rh; CVT_F16X2(rh, d0, d1);
                uint32_t qh; CVT_F16X2(qh, p0, p1);
                dh[u] = rh; mh[u] = qh;
            }
            uint32_t bod = SWZ128((uint32_t)(tid * 128 + g * 16));
            uint32_t bom = SWZ128((uint32_t)(tid * 128 + 64 + g * 16));
            *(uint4*)(sm + SM_B(st) + bod) = make_uint4(dh[0], dh[1], dh[2], dh[3]);
            *(uint4*)(sm + SM_B(st) + bom) = make_uint4(mh[0], mh[1], mh[2], mh[3]);
        }
    };
    auto mmastep = [&](int st, int ks) {
        int kb = ks * 32;
        uint32_t af[4][4], bb[4][4];
#pragma unroll
        for (int am = 0; am < 4; am++) {
            uint32_t off = SWZ128((uint32_t)((wm * 64 + am * 16 + arow) * 128 + kb + aseg * 16));
            ldsm_x4(sb + SM_A(st) + off, af[am]);
        }
#pragma unroll
        for (int bq = 0; bq < 4; bq++) {
            uint32_t off = SWZ128((uint32_t)((wn * 64 + bq * 16 + brow) * 128 + kb + bhalf * 16));
            ldsm_x4(sb + SM_B(st) + off, bb[bq]);
        }
#pragma unroll
        for (int am = 0; am < 4; am++)
#pragma unroll
            for (int bq = 0; bq < 4; bq++) {
                mma16816(acc[am][2 * bq], af[am], bb[bq][0], bb[bq][1]);
                mma16816(acc[am][2 * bq + 1], af[am], bb[bq][2], bb[bq][3]);
            }
    };

    ldgc(0);
    storec(0);
    __syncthreads();
    genf(0);

    for (int kc = 0; kc < 32; kc++) {
        int s = kc & 1, ns = s ^ 1;
        bool have = (kc < 31);
        if (have) ldgc(kc + 1);
        __syncthreads();
        if (have) storec(ns);
        mmastep(s, 0);
        mmastep(s, 1);
        if (have) {
            __syncthreads();
            genf(ns);
        }
        mmastep(s, 2);
        mmastep(s, 3);
    }

    int qrow = lane >> 2, qcol = (lane & 3) * 2;
#pragma unroll
    for (int am = 0; am < 4; am++) {
        int mb = wm * 64 + am * 16;
        float bias0 = b1[m0 + mb + qrow];
        float bias1 = b1[m0 + mb + qrow + 8];
#pragma unroll
        for (int bn = 0; bn < 8; bn++) {
            int n = wn * 64 + bn * 8 + qcol;
#pragma unroll
            for (int r = 0; r < 4; r++) {
                int mrow = mb + qrow + (r >> 1) * 8;
                int nn = n + (r & 1);
                float v = acc[am][bn][r] + ((r >> 1) ? bias1 : bias0);
                v = fmaxf(v, 0.f);
                int sa = nn >> 4, sj = nn & 15;
                int ri = six[sa], rj = six[16 + sj];
                int o = m0 + mrow;
                if (ri >= 0 && rj >= 0) {
                    float* hp = g_h + ((size_t)o << 16);
                    hp[ri * 256 + rj] = v;
                    hp[rj * 256 + ri] = v;
                } else {
                    int pa = i0 + sa, pb = j0 + sj;
                    if (pa == U && rj >= 0)      g_row[(size_t)o * 257 + rj] = v;
                    else if (pb == U && ri >= 0) g_row[(size_t)o * 257 + ri] = v;
                    else if (pa == U && pb == U) g_row[(size_t)o * 257 + 256] = v;
                }
            }
        }
    }
}

// ---------------- 7x7 conv: masked-row factorization + double-buffered prefetch ----------------
__global__ __launch_bounds__(256) void k_conv2(const float* __restrict__ w2) {
    int jb = blockIdx.x, ib = blockIdx.y;
    if (jb < ib) return;
    int g = blockIdx.z;
    __shared__ float sT[2][38][40];
    __shared__ float su[2][40];
    __shared__ float sKc[2][49];
    __shared__ float sS[2][7][32];
    __shared__ int sMi[38], sMj[38];
    int tid = threadIdx.x;
    int tx = tid & 31, ty = tid >> 5;
    int i0 = ib * 32, j0 = jb * 32;
    int rbase = ty * 4;
    float acc[4] = {0.f, 0.f, 0.f, 0.f};

    if (tid < 38) {
        int gi = i0 - 3 + tid;
        sMi[tid] = ((unsigned)gi < 256u) ? ((g_mask[gi] == 0.f) ? 1 : 0) : 2;
        int gj = j0 - 3 + tid;
        sMj[tid] = ((unsigned)gj < 256u) ? ((g_mask[gj] == 0.f) ? 1 : 0) : 2;
    }
    __syncthreads();

    float rT[6], rU, rK;
    auto ldg_stage = [&](int c) {
        const float* hp = g_h + ((size_t)c << 16);
        const float* rw = g_row + (size_t)c * 257;
#pragma unroll
        for (int q = 0; q < 6; q++) {
            rT[q] = 0.f;
            int t = tid + q * 256;
            if (t < 38 * 38) {
                int r = t / 38, cc = t - r * 38;
                if (sMi[r] == 0) {
                    int gi = i0 - 3 + r, gj = j0 - 3 + cc;
                    int mj = sMj[cc];
                    if (mj == 0)      rT[q] = hp[gi * 256 + gj];
                    else if (mj == 1) rT[q] = rw[gi];
                }
            }
        }
        rU = 0.f;
        if (tid < 38) {
            int mj = sMj[tid];
            if (mj == 0)      rU = rw[j0 - 3 + tid];
            else if (mj == 1) rU = rw[256];
        }
        rK = (tid < 49) ? w2[c * 49 + tid] : 0.f;
    };
    auto sts_stage = [&](int s) {
#pragma unroll
        for (int q = 0; q < 6; q++) {
            int t = tid + q * 256;
            if (t < 38 * 38) {
                int r = t / 38, cc = t - r * 38;
                sT[s][r][cc] = rT[q];
            }
        }
        if (tid < 38) su[s][tid] = rU;
        if (tid < 49) sKc[s][tid] = rK;
    };
    auto computeS = [&](int s) {
        if (tid < 224) {
            int a = tid >> 5, j = tid & 31;
            float v = 0.f;
#pragma unroll
            for (int b = 0; b < 7; b++) v += sKc[s][a * 7 + b] * su[s][j + b];
            sS[s][a][j] = v;
        }
    };

    ldg_stage(g * 64);
    sts_stage(0);
    __syncthreads();
    computeS(0);

    for (int ci = 0; ci < 64; ci++) {
        int c = g * 64 + ci;
        int s = ci & 1, ns = s ^ 1;
        bool have = (ci < 63);
        if (have) ldg_stage(c + 1);
        __syncthreads();
        if (have) sts_stage(ns);

        float wk[49];
#pragma unroll
        for (int q = 0; q < 49; q++) wk[q] = sKc[s][q];
#pragma unroll
        for (int rr = 0; rr < 10; rr++) {
            int cls = sMi[rbase + rr];
            if (cls == 0) {
                float seg[7];
#pragma unroll
                for (int b = 0; b < 7; b++) seg[b] = sT[s][rbase + rr][tx + b];
#pragma unroll
                for (int r = 0; r < 4; r++) {
                    int a = rr - r;
                    if (a >= 0 && a < 7) {
#pragma unroll
                        for (int b = 0; b < 7; b++)
                            acc[r] += wk[a * 7 + b] * seg[b];
                    }
                }
            } else if (cls == 1) {
#pragma unroll
                for (int r = 0; r < 4; r++) {
                    int a = rr - r;
                    if (a >= 0 && a < 7) acc[r] += sS[s][a][tx];
                }
            }
        }

        if (have) {
            __syncthreads();
            computeS(ns);
        }
    }

#pragma unroll
    for (int r = 0; r < 4; r++) {
        int i = i0 + rbase + r, j = j0 + tx;
        g_part[g * NPAIR + i * 256 + j] = acc[r];
    }
}

__global__ void k_red(const float* __restrict__ b2, float* __restrict__ out) {
    int idx = blockIdx.x * 256 + threadIdx.x;
    int i = idx >> 8, j = idx & 255;
    if (j < i) return;
    float s = b2[0];
#pragma unroll
    for (int g = 0; g < 16; g++) s += g_part[g * NPAIR + idx];
    float v = 1.f / (1.f + expf(-s));
    out[NEC + i * 256 + j] = v;
    out[NEC + j * 256 + i] = v;
}

extern "C" void kernel_launch(void* const* d_in, const int* in_sizes, int n_in,
                              void* d_out, int out_size) {
    const float* attn    = (const float*)d_in[0];
    const float* pooled  = (const float*)d_in[1];
    const int*   am      = (const int*)d_in[2];
    const float* lin1_w  = (const float*)d_in[3];
    const float* lin1_b  = (const float*)d_in[4];
    const float* cls_w   = (const float*)d_in[5];
    const float* cls_b   = (const float*)d_in[6];
    const float* conv1_w = (const float*)d_in[7];
    const float* conv1_b = (const float*)d_in[8];
    const float* conv2_w = (const float*)d_in[9];
    const float* conv2_b = (const float*)d_in[10];
    float* out = (float*)d_out;

    cudaFuncSetAttribute(k_hmma, cudaFuncAttributeMaxDynamicSharedMemorySize, SMEM_BYTES);

    k_mask<<<1, 256>>>(am);
    k_z<<<256, 256>>>(attn);
    k_wsplit<<<2048, 256>>>(conv1_w);
    k_hmma<<<dim3(8, 17, 17), 256, SMEM_BYTES>>>(conv1_b);
    k_conv2<<<dim3(8, 8, 16), 256>>>(conv2_w);
    k_red<<<256, 256>>>(conv2_b, out);
    k_lin1<<<128, 256>>>(pooled, lin1_w, lin1_b);
    k_cls<<<250, 256>>>(cls_w, cls_b, out);
}